// round 1
// baseline (speedup 1.0000x reference)
#include <cuda_runtime.h>
#include <cuda_bf16.h>

// Problem constants
#define T_   16
#define B_   128
#define N_   2048
#define TB_  (T_ * B_)          // 2048 rows
#define BN_  (B_ * N_)          // 262144
#define TOT_ (T_ * B_ * N_)     // 4194304

// ---------------- scratch (device globals; no allocs allowed) --------------
__device__ float g_h[TB_ * N_];          // GEMM output h [TB, N] (16 MB)
__device__ float g_ssum[T_ * B_];        // spatial_sum [T,B]
__device__ float g_tsum[BN_];            // temporal_sum [B,N]
__device__ float g_psum[32 * N_];        // BN partial sums
__device__ float g_psq[32 * N_];         // BN partial sums of squares
__device__ float g_mu[N_];
__device__ float g_var[N_];

// ---------------- K1a: spatial_sum[t,b] = sum_n x[t,b,n] -------------------
__global__ void spatial_kernel(const float* __restrict__ x) {
    int row = blockIdx.x;                       // t*B + b
    const float4* xr = reinterpret_cast<const float4*>(x + (size_t)row * N_);
    float s = 0.f;
    #pragma unroll
    for (int i = 0; i < 2; i++) {
        float4 v = xr[threadIdx.x + i * 256];
        s += v.x + v.y + v.z + v.w;
    }
    // block reduce (256 threads)
    __shared__ float red[8];
    for (int off = 16; off > 0; off >>= 1)
        s += __shfl_down_sync(0xffffffffu, s, off);
    if ((threadIdx.x & 31) == 0) red[threadIdx.x >> 5] = s;
    __syncthreads();
    if (threadIdx.x < 8) {
        s = red[threadIdx.x];
        for (int off = 4; off > 0; off >>= 1)
            s += __shfl_down_sync(0xffu, s, off);
        if (threadIdx.x == 0) g_ssum[row] = s;
    }
}

// ---------------- K1b: temporal_sum[b,n] = sum_t x[t,b,n] ------------------
__global__ void temporal_kernel(const float* __restrict__ x) {
    int idx = blockIdx.x * 256 + threadIdx.x;   // b*N + n
    float s = 0.f;
    #pragma unroll
    for (int t = 0; t < T_; t++) s += x[(size_t)t * BN_ + idx];
    g_tsum[idx] = s;
}

// ---------------- K2: GEMM  h[r,m] = sum_k x[r,k]*W[m,k] -------------------
// Both operands K-contiguous ("NT"). 128x128 tile, BK=16, 8x8 microtile.
#define BM 128
#define BNC 128
#define BK 16

__global__ __launch_bounds__(256, 2)
void gemm_nt_kernel(const float* __restrict__ A, const float* __restrict__ W,
                    float* __restrict__ C) {
    __shared__ float As[BK][BM];
    __shared__ float Bs[BK][BNC];

    const int tid = threadIdx.x;
    const int tx = tid & 15;         // 0..15  -> output col group
    const int ty = tid >> 4;         // 0..15  -> output row group
    const int rowBase = blockIdx.y * BM;
    const int colBase = blockIdx.x * BNC;

    float acc[8][8];
    #pragma unroll
    for (int i = 0; i < 8; i++)
        #pragma unroll
        for (int j = 0; j < 8; j++) acc[i][j] = 0.f;

    for (int k0 = 0; k0 < N_; k0 += BK) {
        // load A tile (128 rows x 16 k) : 512 float4, 2 per thread
        #pragma unroll
        for (int i = 0; i < 2; i++) {
            int f = i * 256 + tid;          // 0..511
            int r = f >> 2;                 // row in tile
            int kq = f & 3;                 // which float4 in the 16-wide row
            float4 v = *reinterpret_cast<const float4*>(
                A + (size_t)(rowBase + r) * N_ + k0 + kq * 4);
            As[kq * 4 + 0][r] = v.x;
            As[kq * 4 + 1][r] = v.y;
            As[kq * 4 + 2][r] = v.z;
            As[kq * 4 + 3][r] = v.w;
        }
        // load B tile (128 output-cols x 16 k) from W
        #pragma unroll
        for (int i = 0; i < 2; i++) {
            int f = i * 256 + tid;
            int r = f >> 2;
            int kq = f & 3;
            float4 v = *reinterpret_cast<const float4*>(
                W + (size_t)(colBase + r) * N_ + k0 + kq * 4);
            Bs[kq * 4 + 0][r] = v.x;
            Bs[kq * 4 + 1][r] = v.y;
            Bs[kq * 4 + 2][r] = v.z;
            Bs[kq * 4 + 3][r] = v.w;
        }
        __syncthreads();

        #pragma unroll
        for (int k = 0; k < BK; k++) {
            float ar[8], br[8];
            *reinterpret_cast<float4*>(ar)     = *reinterpret_cast<const float4*>(&As[k][ty * 8]);
            *reinterpret_cast<float4*>(ar + 4) = *reinterpret_cast<const float4*>(&As[k][ty * 8 + 4]);
            *reinterpret_cast<float4*>(br)     = *reinterpret_cast<const float4*>(&Bs[k][tx * 8]);
            *reinterpret_cast<float4*>(br + 4) = *reinterpret_cast<const float4*>(&Bs[k][tx * 8 + 4]);
            #pragma unroll
            for (int i = 0; i < 8; i++)
                #pragma unroll
                for (int j = 0; j < 8; j++)
                    acc[i][j] = fmaf(ar[i], br[j], acc[i][j]);
        }
        __syncthreads();
    }

    // write back (float4 stores)
    #pragma unroll
    for (int i = 0; i < 8; i++) {
        size_t base = (size_t)(rowBase + ty * 8 + i) * N_ + colBase + tx * 8;
        *reinterpret_cast<float4*>(C + base)     = *reinterpret_cast<const float4*>(&acc[i][0]);
        *reinterpret_cast<float4*>(C + base + 4) = *reinterpret_cast<const float4*>(&acc[i][4]);
    }
}

// ---------------- K3a: BN partial stats per column --------------------------
__global__ void bn_partial_kernel() {
    int col = blockIdx.x * 256 + threadIdx.x;   // feature m
    int rc  = blockIdx.y;                       // row chunk 0..31 (64 rows each)
    float s = 0.f, sq = 0.f;
    #pragma unroll 4
    for (int r = 0; r < 64; r++) {
        float h = g_h[(size_t)(rc * 64 + r) * N_ + col];
        s += h;
        sq = fmaf(h, h, sq);
    }
    g_psum[rc * N_ + col] = s;
    g_psq [rc * N_ + col] = sq;
}

// ---------------- K3b: finalize mu/var --------------------------------------
__global__ void bn_final_kernel() {
    int col = blockIdx.x * 256 + threadIdx.x;
    float s = 0.f, sq = 0.f;
    #pragma unroll
    for (int rc = 0; rc < 32; rc++) {
        s  += g_psum[rc * N_ + col];
        sq += g_psq [rc * N_ + col];
    }
    float mu = s * (1.0f / TB_);
    g_mu[col]  = mu;
    g_var[col] = sq * (1.0f / TB_) - mu * mu;
}

// ---------------- K4: fused BN + 3x LIF + combine ---------------------------
// Three LIF recurrences advance in lock-step over t:
//   v = 0.5*v + in ; s = (v>=1) ; v = s ? 0 : v   (TAU=2, VTH=1, hard reset 0)
__global__ void fused_lif_kernel(const float* __restrict__ x,
                                 const float* __restrict__ gamma,
                                 const float* __restrict__ beta,
                                 float* __restrict__ out) {
    int idx = blockIdx.x * 256 + threadIdx.x;   // b*N + n
    int n = idx & (N_ - 1);
    int b = idx >> 11;

    float mu    = g_mu[n];
    float scale = gamma[n] * rsqrtf(g_var[n] + 1e-5f);
    float bet   = beta[n];
    float tsum  = g_tsum[idx];

    float v1 = 0.f, v2 = 0.f, v3 = 0.f;
    #pragma unroll
    for (int t = 0; t < T_; t++) {
        size_t off = (size_t)t * BN_ + idx;
        float h  = g_h[off];
        float hn = (h - mu) * scale + bet;

        v1 = 0.5f * v1 + hn;
        float s1 = (v1 >= 1.0f) ? 1.0f : 0.0f;
        v1 = (v1 >= 1.0f) ? 0.0f : v1;

        float ss = g_ssum[t * B_ + b];
        v2 = 0.5f * v2 + s1 * ss;
        float s2 = (v2 >= 1.0f) ? 1.0f : 0.0f;
        v2 = (v2 >= 1.0f) ? 0.0f : v2;

        v3 = 0.5f * v3 + s1 * tsum;
        float s3 = (v3 >= 1.0f) ? 1.0f : 0.0f;
        v3 = (v3 >= 1.0f) ? 0.0f : v3;

        out[off] = x[off] + s2 * s3;
    }
}

// ---------------- launch -----------------------------------------------------
extern "C" void kernel_launch(void* const* d_in, const int* in_sizes, int n_in,
                              void* d_out, int out_size) {
    const float* x     = (const float*)d_in[0];   // [T,B,N]
    const float* W     = (const float*)d_in[1];   // [N,N]
    const float* gamma = (const float*)d_in[2];
    const float* beta  = (const float*)d_in[3];
    float* out = (float*)d_out;

    float* h;
    cudaGetSymbolAddress((void**)&h, g_h);

    spatial_kernel<<<TB_, 256>>>(x);
    temporal_kernel<<<BN_ / 256, 256>>>(x);

    dim3 gemmGrid(N_ / BNC, TB_ / BM);
    gemm_nt_kernel<<<gemmGrid, 256>>>(x, W, h);

    dim3 bnGrid(N_ / 256, 32);
    bn_partial_kernel<<<bnGrid, 256>>>();
    bn_final_kernel<<<N_ / 256, 256>>>();

    fused_lif_kernel<<<BN_ / 256, 256>>>(x, gamma, beta, out);
}

// round 3
// speedup vs baseline: 1.4369x; 1.4369x over previous
#include <cuda_runtime.h>
#include <cuda_bf16.h>
#include <cstdint>

// Problem constants
#define T_   16
#define B_   128
#define N_   2048
#define TB_  (T_ * B_)          // 2048 rows
#define BN_  (B_ * N_)          // 262144

// ---------------- scratch (device globals; no allocs allowed) --------------
__device__ float g_h[TB_ * N_];          // GEMM output h [TB, N] (16 MB)
__device__ float g_ssum[T_ * B_];        // spatial_sum [T,B]
__device__ float g_tsum[BN_];            // temporal_sum [B,N]
__device__ float g_psum[128 * N_];       // BN partial sums
__device__ float g_psq[128 * N_];        // BN partial sums of squares
__device__ float g_mu[N_];
__device__ float g_var[N_];

// ======================= helpers ===========================================
__device__ __forceinline__ uint32_t smem_u32(const void* p) {
    uint32_t a;
    asm("{ .reg .u64 t; cvta.to.shared.u64 t, %1; cvt.u32.u64 %0, t; }"
        : "=r"(a) : "l"(p));
    return a;
}

__device__ __forceinline__ float tf32_rna(float x) {
    uint32_t u;
    asm("cvt.rna.tf32.f32 %0, %1;" : "=r"(u) : "f"(x));
    return __uint_as_float(u);
}

__device__ __forceinline__ void ldsm_x4(uint32_t addr, uint32_t& r0, uint32_t& r1,
                                        uint32_t& r2, uint32_t& r3) {
    asm volatile("ldmatrix.sync.aligned.m8n8.x4.shared.b16 {%0,%1,%2,%3}, [%4];"
                 : "=r"(r0), "=r"(r1), "=r"(r2), "=r"(r3) : "r"(addr));
}

__device__ __forceinline__ void mma_tf32(float* c, const uint32_t* a,
                                         uint32_t b0, uint32_t b1) {
    asm volatile(
        "mma.sync.aligned.m16n8k8.row.col.f32.tf32.tf32.f32 "
        "{%0,%1,%2,%3}, {%4,%5,%6,%7}, {%8,%9}, {%0,%1,%2,%3};\n"
        : "+f"(c[0]), "+f"(c[1]), "+f"(c[2]), "+f"(c[3])
        : "r"(a[0]), "r"(a[1]), "r"(a[2]), "r"(a[3]), "r"(b0), "r"(b1));
}

__device__ __forceinline__ void split4(float4 v, float4& hi, float4& lo) {
    hi.x = tf32_rna(v.x); lo.x = v.x - hi.x;
    hi.y = tf32_rna(v.y); lo.y = v.y - hi.y;
    hi.z = tf32_rna(v.z); lo.z = v.z - hi.z;
    hi.w = tf32_rna(v.w); lo.w = v.w - hi.w;
}

// ======================= K1a: spatial_sum ===================================
__global__ void spatial_kernel(const float* __restrict__ x) {
    int row = blockIdx.x;                       // t*B + b
    const float4* xr = reinterpret_cast<const float4*>(x + (size_t)row * N_);
    float s = 0.f;
    #pragma unroll
    for (int i = 0; i < 2; i++) {
        float4 v = xr[threadIdx.x + i * 256];
        s += v.x + v.y + v.z + v.w;
    }
    __shared__ float red[8];
    for (int off = 16; off > 0; off >>= 1)
        s += __shfl_down_sync(0xffffffffu, s, off);
    if ((threadIdx.x & 31) == 0) red[threadIdx.x >> 5] = s;
    __syncthreads();
    if (threadIdx.x < 8) {
        s = red[threadIdx.x];
        for (int off = 4; off > 0; off >>= 1)
            s += __shfl_down_sync(0xffu, s, off);
        if (threadIdx.x == 0) g_ssum[row] = s;
    }
}

// ======================= K1b: temporal_sum ==================================
__global__ void temporal_kernel(const float* __restrict__ x) {
    int idx4 = blockIdx.x * 256 + threadIdx.x;   // float4 index into [B,N]
    const float4* x4 = reinterpret_cast<const float4*>(x);
    float4 s = make_float4(0.f, 0.f, 0.f, 0.f);
    #pragma unroll
    for (int t = 0; t < T_; t++) {
        float4 v = x4[(size_t)t * (BN_ / 4) + idx4];
        s.x += v.x; s.y += v.y; s.z += v.z; s.w += v.w;
    }
    reinterpret_cast<float4*>(g_tsum)[idx4] = s;
}

// ======================= K2: mma.sync tf32x3 GEMM ===========================
// h[r,m] = sum_k x[r,k] * W[m,k].
// CTA tile 128(M) x 128(N) x 16(K), 256 threads = 8 warps (2x4), warp 64x32.
// tf32 split: hi = rna(x), lo = x - hi; keep hh + hl + lh.
#define BK     16
#define SKEW   20                      // floats per smem row (16 + 4 pad)
#define TILEF  (128 * SKEW)            // floats per region
#define STAGEF (4 * TILEF)             // A_hi, A_lo, B_hi, B_lo
#define GEMM_SMEM (2 * STAGEF * 4)     // 81920 bytes

__global__ __launch_bounds__(256, 2)
void gemm_mma_kernel(const float* __restrict__ A, const float* __restrict__ W,
                     float* __restrict__ C) {
    extern __shared__ float sm[];
    const uint32_t sbase = smem_u32(sm);
    const int tid  = threadIdx.x;
    const int wid  = tid >> 5;
    const int lane = tid & 31;
    const int wm = wid >> 2;            // 0..1 -> 64-row slab
    const int wn = wid & 3;             // 0..3 -> 32-col slab
    const int rowBase = blockIdx.y * 128;
    const int colBase = blockIdx.x * 128;

    // ---- accumulators: 4 m-tiles x 4 n-tiles x 4 regs ----
    float acc[4][4][4];
    #pragma unroll
    for (int i = 0; i < 4; i++)
        #pragma unroll
        for (int j = 0; j < 4; j++)
            #pragma unroll
            for (int c = 0; c < 4; c++) acc[i][j][c] = 0.f;

    // ---- gmem loader mapping: 256 threads, 128 rows x 16 floats per tile ----
    const int lr = tid >> 1;            // row 0..127
    const int lq = (tid & 1) * 8;       // float offset (two float4 halves)
    const float* Ag = A + (size_t)(rowBase + lr) * N_ + lq;
    const float* Wg = W + (size_t)(colBase + lr) * N_ + lq;
    const int sOff = lr * SKEW + lq;    // float offset within region

    // ---- ldmatrix per-lane addresses (byte offsets into smem) ----
    // A frag (m16k8): lanes 0-7: rows 0-7 k0-3; 8-15: rows 8-15 k0-3;
    //                 16-23: rows 0-7 k4-7;  24-31: rows 8-15 k4-7
    const int a_row = (lane & 7) + ((lane >> 3) & 1) * 8;
    const int a_col = ((lane >> 4) & 1) * 4;
    // B frag pair (two n8 tiles): lanes 0-7: rows 0-7 k0-3; 8-15: rows 0-7 k4-7;
    //                 16-23: rows 8-15 k0-3; 24-31: rows 8-15 k4-7
    const int b_row = (lane & 7) + ((lane >> 4) & 1) * 8;
    const int b_col = ((lane >> 3) & 1) * 4;

    const uint32_t aAddr0 = sbase + (uint32_t)(((wm * 64 + a_row) * SKEW + a_col) * 4);
    const uint32_t bAddr0 = sbase + (uint32_t)((2 * TILEF + (wn * 32 + b_row) * SKEW + b_col) * 4);
    const uint32_t stageB = STAGEF * 4;
    const uint32_t tileB  = TILEF * 4;

    // ---- preload chunk 0 into stage 0 ----
    {
        float4 hi, lo;
        float4 va0 = *reinterpret_cast<const float4*>(Ag);
        float4 va1 = *reinterpret_cast<const float4*>(Ag + 4);
        float4 vb0 = *reinterpret_cast<const float4*>(Wg);
        float4 vb1 = *reinterpret_cast<const float4*>(Wg + 4);
        split4(va0, hi, lo);
        *reinterpret_cast<float4*>(sm + sOff)              = hi;
        *reinterpret_cast<float4*>(sm + TILEF + sOff)      = lo;
        split4(va1, hi, lo);
        *reinterpret_cast<float4*>(sm + sOff + 4)          = hi;
        *reinterpret_cast<float4*>(sm + TILEF + sOff + 4)  = lo;
        split4(vb0, hi, lo);
        *reinterpret_cast<float4*>(sm + 2 * TILEF + sOff)     = hi;
        *reinterpret_cast<float4*>(sm + 3 * TILEF + sOff)     = lo;
        split4(vb1, hi, lo);
        *reinterpret_cast<float4*>(sm + 2 * TILEF + sOff + 4) = hi;
        *reinterpret_cast<float4*>(sm + 3 * TILEF + sOff + 4) = lo;
    }
    __syncthreads();

    const int NCHUNK = N_ / BK;          // 128
    #pragma unroll 1
    for (int kc = 0; kc < NCHUNK; kc++) {
        const int st = kc & 1;
        const uint32_t aS = aAddr0 + st * stageB;
        const uint32_t bS = bAddr0 + st * stageB;

        // prefetch next chunk (gmem only; STS after compute)
        float4 va0, va1, vb0, vb1;
        const bool pf = (kc + 1 < NCHUNK);
        if (pf) {
            const float* Agk = Ag + (kc + 1) * BK;
            const float* Wgk = Wg + (kc + 1) * BK;
            va0 = *reinterpret_cast<const float4*>(Agk);
            va1 = *reinterpret_cast<const float4*>(Agk + 4);
            vb0 = *reinterpret_cast<const float4*>(Wgk);
            vb1 = *reinterpret_cast<const float4*>(Wgk + 4);
        }

        // ---- compute: 2 ksteps x (hh + hl + lh) ----
        #pragma unroll
        for (int ks = 0; ks < 2; ks++) {
            const uint32_t kb = ks * 32;         // 8 floats
            uint32_t a[4][4];
            // A_hi frags
            #pragma unroll
            for (int i = 0; i < 4; i++)
                ldsm_x4(aS + kb + i * (16 * SKEW * 4), a[i][0], a[i][1], a[i][2], a[i][3]);
            #pragma unroll
            for (int j = 0; j < 2; j++) {
                uint32_t bh[4], bl[4];
                ldsm_x4(bS + kb + j * (16 * SKEW * 4), bh[0], bh[1], bh[2], bh[3]);
                ldsm_x4(bS + tileB + kb + j * (16 * SKEW * 4), bl[0], bl[1], bl[2], bl[3]);
                #pragma unroll
                for (int i = 0; i < 4; i++) {
                    mma_tf32(acc[i][2 * j],     a[i], bh[0], bh[1]);
                    mma_tf32(acc[i][2 * j + 1], a[i], bh[2], bh[3]);
                    mma_tf32(acc[i][2 * j],     a[i], bl[0], bl[1]);
                    mma_tf32(acc[i][2 * j + 1], a[i], bl[2], bl[3]);
                }
            }
            // A_lo frags (reuse a[][])
            #pragma unroll
            for (int i = 0; i < 4; i++)
                ldsm_x4(aS + tileB + kb + i * (16 * SKEW * 4), a[i][0], a[i][1], a[i][2], a[i][3]);
            #pragma unroll
            for (int j = 0; j < 2; j++) {
                uint32_t bh[4];
                ldsm_x4(bS + kb + j * (16 * SKEW * 4), bh[0], bh[1], bh[2], bh[3]);
                #pragma unroll
                for (int i = 0; i < 4; i++) {
                    mma_tf32(acc[i][2 * j],     a[i], bh[0], bh[1]);
                    mma_tf32(acc[i][2 * j + 1], a[i], bh[2], bh[3]);
                }
            }
        }

        // ---- split + STS next chunk into other stage ----
        if (pf) {
            float* smn = sm + (st ^ 1) * STAGEF;
            float4 hi, lo;
            split4(va0, hi, lo);
            *reinterpret_cast<float4*>(smn + sOff)             = hi;
            *reinterpret_cast<float4*>(smn + TILEF + sOff)     = lo;
            split4(va1, hi, lo);
            *reinterpret_cast<float4*>(smn + sOff + 4)         = hi;
            *reinterpret_cast<float4*>(smn + TILEF + sOff + 4) = lo;
            split4(vb0, hi, lo);
            *reinterpret_cast<float4*>(smn + 2 * TILEF + sOff)     = hi;
            *reinterpret_cast<float4*>(smn + 3 * TILEF + sOff)     = lo;
            split4(vb1, hi, lo);
            *reinterpret_cast<float4*>(smn + 2 * TILEF + sOff + 4) = hi;
            *reinterpret_cast<float4*>(smn + 3 * TILEF + sOff + 4) = lo;
        }
        __syncthreads();
    }

    // ---- epilogue: write 128x128 tile ----
    const int gid = lane >> 2;
    const int qd  = lane & 3;
    const int m0 = rowBase + wm * 64 + gid;
    const int n0 = colBase + wn * 32 + 2 * qd;
    #pragma unroll
    for (int i = 0; i < 4; i++) {
        #pragma unroll
        for (int jj = 0; jj < 4; jj++) {
            float* p = C + (size_t)(m0 + 16 * i) * N_ + n0 + 8 * jj;
            float2 v01 = make_float2(acc[i][jj][0], acc[i][jj][1]);
            float2 v23 = make_float2(acc[i][jj][2], acc[i][jj][3]);
            *reinterpret_cast<float2*>(p)          = v01;
            *reinterpret_cast<float2*>(p + 8 * N_) = v23;
        }
    }
}

// ======================= K3a: BN partial stats ==============================
__global__ void bn_partial_kernel() {
    int col = blockIdx.x * 256 + threadIdx.x;   // feature m
    int rc  = blockIdx.y;                       // row chunk 0..127 (16 rows each)
    float s = 0.f, sq = 0.f;
    #pragma unroll
    for (int rr = 0; rr < 16; rr++) {
        float h = g_h[(size_t)(rc * 16 + rr) * N_ + col];
        s += h;
        sq = fmaf(h, h, sq);
    }
    g_psum[rc * N_ + col] = s;
    g_psq [rc * N_ + col] = sq;
}

// ======================= K3b: finalize mu/var ===============================
__global__ void bn_final_kernel() {
    int col = blockIdx.x * 256 + threadIdx.x;
    float s = 0.f, sq = 0.f;
    #pragma unroll 8
    for (int rc = 0; rc < 128; rc++) {
        s  += g_psum[rc * N_ + col];
        sq += g_psq [rc * N_ + col];
    }
    float mu = s * (1.0f / TB_);
    g_mu[col]  = mu;
    g_var[col] = sq * (1.0f / TB_) - mu * mu;
}

// ======================= K4: fused BN + 3x LIF + combine ====================
__global__ void fused_lif_kernel(const float* __restrict__ x,
                                 const float* __restrict__ gamma,
                                 const float* __restrict__ beta,
                                 float* __restrict__ out) {
    int idx4 = blockIdx.x * 256 + threadIdx.x;   // float4 index into [B,N]
    int b  = idx4 >> 9;
    int n4 = idx4 & 511;

    float4 mu4  = reinterpret_cast<const float4*>(g_mu)[n4];
    float4 var4 = reinterpret_cast<const float4*>(g_var)[n4];
    float4 ga4  = reinterpret_cast<const float4*>(gamma)[n4];
    float4 be4  = reinterpret_cast<const float4*>(beta)[n4];
    float4 ts4  = reinterpret_cast<const float4*>(g_tsum)[idx4];

    float mu[4]    = {mu4.x, mu4.y, mu4.z, mu4.w};
    float scale[4] = {ga4.x * rsqrtf(var4.x + 1e-5f), ga4.y * rsqrtf(var4.y + 1e-5f),
                      ga4.z * rsqrtf(var4.z + 1e-5f), ga4.w * rsqrtf(var4.w + 1e-5f)};
    float bet[4]   = {be4.x, be4.y, be4.z, be4.w};
    float ts[4]    = {ts4.x, ts4.y, ts4.z, ts4.w};

    float v1[4] = {0, 0, 0, 0}, v2[4] = {0, 0, 0, 0}, v3[4] = {0, 0, 0, 0};
    const float4* h4 = reinterpret_cast<const float4*>(g_h);
    const float4* x4 = reinterpret_cast<const float4*>(x);
    float4* o4 = reinterpret_cast<float4*>(out);

    #pragma unroll
    for (int t = 0; t < T_; t++) {
        size_t off = (size_t)t * (BN_ / 4) + idx4;
        float4 hv = h4[off];
        float4 xv = x4[off];
        float hh[4] = {hv.x, hv.y, hv.z, hv.w};
        float xx[4] = {xv.x, xv.y, xv.z, xv.w};
        float ss = g_ssum[t * B_ + b];
        float res[4];
        #pragma unroll
        for (int j = 0; j < 4; j++) {
            float hn = (hh[j] - mu[j]) * scale[j] + bet[j];
            v1[j] = 0.5f * v1[j] + hn;
            float s1 = (v1[j] >= 1.0f) ? 1.0f : 0.0f;
            v1[j] = (v1[j] >= 1.0f) ? 0.0f : v1[j];
            v2[j] = 0.5f * v2[j] + s1 * ss;
            float s2 = (v2[j] >= 1.0f) ? 1.0f : 0.0f;
            v2[j] = (v2[j] >= 1.0f) ? 0.0f : v2[j];
            v3[j] = 0.5f * v3[j] + s1 * ts[j];
            float s3 = (v3[j] >= 1.0f) ? 1.0f : 0.0f;
            v3[j] = (v3[j] >= 1.0f) ? 0.0f : v3[j];
            res[j] = xx[j] + s2 * s3;
        }
        o4[off] = make_float4(res[0], res[1], res[2], res[3]);
    }
}

// ======================= launch =============================================
extern "C" void kernel_launch(void* const* d_in, const int* in_sizes, int n_in,
                              void* d_out, int out_size) {
    const float* x     = (const float*)d_in[0];   // [T,B,N]
    const float* W     = (const float*)d_in[1];   // [N,N]
    const float* gamma = (const float*)d_in[2];
    const float* beta  = (const float*)d_in[3];
    float* out = (float*)d_out;

    float* h;
    cudaGetSymbolAddress((void**)&h, g_h);

    cudaFuncSetAttribute(gemm_mma_kernel,
                         cudaFuncAttributeMaxDynamicSharedMemorySize, GEMM_SMEM);

    spatial_kernel<<<TB_, 256>>>(x);
    temporal_kernel<<<BN_ / 1024, 256>>>(x);

    dim3 gemmGrid(N_ / 128, TB_ / 128);
    gemm_mma_kernel<<<gemmGrid, 256, GEMM_SMEM>>>(x, W, h);

    dim3 bnGrid(N_ / 256, 128);
    bn_partial_kernel<<<bnGrid, 256>>>();
    bn_final_kernel<<<N_ / 256, 256>>>();

    fused_lif_kernel<<<BN_ / 1024, 256>>>(x, gamma, beta, out);
}

// round 4
// speedup vs baseline: 1.4531x; 1.0113x over previous
#include <cuda_runtime.h>
#include <cuda_bf16.h>
#include <cstdint>

// Problem constants
#define T_   16
#define B_   128
#define N_   2048
#define TB_  (T_ * B_)          // 2048 rows
#define BN_  (B_ * N_)          // 262144

// ---------------- scratch (device globals; no allocs allowed) --------------
__device__ float g_h[TB_ * N_];          // GEMM output h [TB, N] (16 MB)
__device__ float g_ssum[T_ * B_];        // spatial_sum [T,B]
__device__ float g_tsum[BN_];            // temporal_sum [B,N]
__device__ float g_psum[128 * N_];       // BN partial sums
__device__ float g_psq[128 * N_];        // BN partial sums of squares
__device__ float g_mu[N_];
__device__ float g_var[N_];

// ======================= helpers ===========================================
__device__ __forceinline__ uint32_t smem_u32(const void* p) {
    uint32_t a;
    asm("{ .reg .u64 t; cvta.to.shared.u64 t, %1; cvt.u32.u64 %0, t; }"
        : "=r"(a) : "l"(p));
    return a;
}

__device__ __forceinline__ float tf32_rna(float x) {
    uint32_t u;
    asm("cvt.rna.tf32.f32 %0, %1;" : "=r"(u) : "f"(x));
    return __uint_as_float(u);
}

__device__ __forceinline__ void ldsm_x4(uint32_t addr, uint32_t& r0, uint32_t& r1,
                                        uint32_t& r2, uint32_t& r3) {
    asm volatile("ldmatrix.sync.aligned.m8n8.x4.shared.b16 {%0,%1,%2,%3}, [%4];"
                 : "=r"(r0), "=r"(r1), "=r"(r2), "=r"(r3) : "r"(addr));
}

__device__ __forceinline__ void mma_tf32(float* c, const uint32_t* a,
                                         uint32_t b0, uint32_t b1) {
    asm volatile(
        "mma.sync.aligned.m16n8k8.row.col.f32.tf32.tf32.f32 "
        "{%0,%1,%2,%3}, {%4,%5,%6,%7}, {%8,%9}, {%0,%1,%2,%3};\n"
        : "+f"(c[0]), "+f"(c[1]), "+f"(c[2]), "+f"(c[3])
        : "r"(a[0]), "r"(a[1]), "r"(a[2]), "r"(a[3]), "r"(b0), "r"(b1));
}

#define CP_ASYNC16(dst, src) \
    asm volatile("cp.async.ca.shared.global [%0], [%1], 16;" :: "r"(dst), "l"(src))
#define CP_COMMIT() asm volatile("cp.async.commit_group;" ::: "memory")
#define CP_WAIT1()  asm volatile("cp.async.wait_group 1;" ::: "memory")

// split a raw fragment (4 regs of fp32 bit patterns) into tf32 hi/lo
__device__ __forceinline__ void split_frag(const uint32_t* r, uint32_t* hi, uint32_t* lo) {
    #pragma unroll
    for (int c = 0; c < 4; c++) {
        float v = __uint_as_float(r[c]);
        float h = tf32_rna(v);
        float l = tf32_rna(v - h);
        hi[c] = __float_as_uint(h);
        lo[c] = __float_as_uint(l);
    }
}

// ======================= K1a: spatial_sum ===================================
__global__ void spatial_kernel(const float* __restrict__ x) {
    int row = blockIdx.x;                       // t*B + b
    const float4* xr = reinterpret_cast<const float4*>(x + (size_t)row * N_);
    float s = 0.f;
    #pragma unroll
    for (int i = 0; i < 2; i++) {
        float4 v = xr[threadIdx.x + i * 256];
        s += v.x + v.y + v.z + v.w;
    }
    __shared__ float red[8];
    for (int off = 16; off > 0; off >>= 1)
        s += __shfl_down_sync(0xffffffffu, s, off);
    if ((threadIdx.x & 31) == 0) red[threadIdx.x >> 5] = s;
    __syncthreads();
    if (threadIdx.x < 8) {
        s = red[threadIdx.x];
        for (int off = 4; off > 0; off >>= 1)
            s += __shfl_down_sync(0xffu, s, off);
        if (threadIdx.x == 0) g_ssum[row] = s;
    }
}

// ======================= K1b: temporal_sum ==================================
__global__ void temporal_kernel(const float* __restrict__ x) {
    int idx4 = blockIdx.x * 256 + threadIdx.x;   // float4 index into [B,N]
    const float4* x4 = reinterpret_cast<const float4*>(x);
    float4 s = make_float4(0.f, 0.f, 0.f, 0.f);
    #pragma unroll
    for (int t = 0; t < T_; t++) {
        float4 v = x4[(size_t)t * (BN_ / 4) + idx4];
        s.x += v.x; s.y += v.y; s.z += v.z; s.w += v.w;
    }
    reinterpret_cast<float4*>(g_tsum)[idx4] = s;
}

// ======================= K2: mma.sync tf32x3 GEMM ===========================
// h[r,m] = sum_k x[r,k] * W[m,k].
// CTA tile 128(M) x 128(N) x 32(K), 256 threads = 8 warps (2x4), warp 64x32.
// Raw fp32 tiles in smem via cp.async double-buffer; tf32 hi/lo split in regs.
#define BK     32
#define ROWF   36                      // floats per smem row (32 + 4 pad)
#define TILEF  (128 * ROWF)            // 4608 floats per tile
#define TILEB  (TILEF * 4)             // 18432 bytes
#define STAGEB (2 * TILEB)             // A + B raw: 36864 bytes
#define GEMM_SMEM (2 * STAGEB)         // 73728 bytes

__global__ __launch_bounds__(256, 2)
void gemm_mma_kernel(const float* __restrict__ A, const float* __restrict__ W,
                     float* __restrict__ C) {
    extern __shared__ float sm[];
    const uint32_t sbase = smem_u32(sm);
    const int tid  = threadIdx.x;
    const int wid  = tid >> 5;
    const int lane = tid & 31;
    const int wm = wid >> 2;            // 0..1 -> 64-row slab
    const int wn = wid & 3;             // 0..3 -> 32-col slab
    const int rowBase = blockIdx.y * 128;
    const int colBase = blockIdx.x * 128;

    float acc[4][4][4];
    #pragma unroll
    for (int i = 0; i < 4; i++)
        #pragma unroll
        for (int j = 0; j < 4; j++)
            #pragma unroll
            for (int c = 0; c < 4; c++) acc[i][j][c] = 0.f;

    // ---- cp.async loader: thread -> (row, 16-float half-row) ----
    const int lrow = tid >> 1;                  // 0..127
    const int lq   = (tid & 1) * 16;            // float offset within row
    const float* Ag = A + (size_t)(rowBase + lrow) * N_ + lq;
    const float* Wg = W + (size_t)(colBase + lrow) * N_ + lq;
    const uint32_t sA = sbase + (uint32_t)((lrow * ROWF + lq) * 4);
    const uint32_t sB = sA + TILEB;

    // ---- ldmatrix per-lane addresses ----
    const int a_row = (lane & 7) + ((lane >> 3) & 1) * 8;
    const int a_col = ((lane >> 4) & 1) * 4;
    const int b_row = (lane & 7) + ((lane >> 4) & 1) * 8;
    const int b_col = ((lane >> 3) & 1) * 4;
    const uint32_t aBase = sbase + (uint32_t)(((wm * 64 + a_row) * ROWF + a_col) * 4);
    const uint32_t bBase = sbase + TILEB + (uint32_t)(((wn * 32 + b_row) * ROWF + b_col) * 4);

    // prologue: stages 0 and 1
    #pragma unroll
    for (int s = 0; s < 2; s++) {
        const float* a = Ag + s * BK;
        const float* w = Wg + s * BK;
        #pragma unroll
        for (int j = 0; j < 4; j++) {
            CP_ASYNC16(sA + s * STAGEB + j * 16, a + j * 4);
            CP_ASYNC16(sB + s * STAGEB + j * 16, w + j * 4);
        }
        CP_COMMIT();
    }

    const int NCHUNK = N_ / BK;          // 64
    #pragma unroll 1
    for (int kc = 0; kc < NCHUNK; kc++) {
        const int st = kc & 1;
        CP_WAIT1();
        __syncthreads();

        const uint32_t aS = aBase + st * STAGEB;
        const uint32_t bS = bBase + st * STAGEB;

        #pragma unroll
        for (int ks = 0; ks < 4; ks++) {
            const uint32_t kb = ks * 32;         // 8 floats
            #pragma unroll
            for (int j = 0; j < 2; j++) {
                uint32_t br[4], bhi[4], blo[4];
                ldsm_x4(bS + j * (16 * ROWF * 4) + kb, br[0], br[1], br[2], br[3]);
                split_frag(br, bhi, blo);
                #pragma unroll
                for (int ih = 0; ih < 4; ih += 2) {
                    uint32_t r0[4], r1[4];
                    uint32_t h0[4], l0[4], h1[4], l1[4];
                    ldsm_x4(aS + ih       * (16 * ROWF * 4) + kb, r0[0], r0[1], r0[2], r0[3]);
                    ldsm_x4(aS + (ih + 1) * (16 * ROWF * 4) + kb, r1[0], r1[1], r1[2], r1[3]);
                    split_frag(r0, h0, l0);
                    split_frag(r1, h1, l1);
                    // hh
                    mma_tf32(acc[ih][2 * j],         h0, bhi[0], bhi[1]);
                    mma_tf32(acc[ih + 1][2 * j],     h1, bhi[0], bhi[1]);
                    mma_tf32(acc[ih][2 * j + 1],     h0, bhi[2], bhi[3]);
                    mma_tf32(acc[ih + 1][2 * j + 1], h1, bhi[2], bhi[3]);
                    // lh
                    mma_tf32(acc[ih][2 * j],         l0, bhi[0], bhi[1]);
                    mma_tf32(acc[ih + 1][2 * j],     l1, bhi[0], bhi[1]);
                    mma_tf32(acc[ih][2 * j + 1],     l0, bhi[2], bhi[3]);
                    mma_tf32(acc[ih + 1][2 * j + 1], l1, bhi[2], bhi[3]);
                    // hl
                    mma_tf32(acc[ih][2 * j],         h0, blo[0], blo[1]);
                    mma_tf32(acc[ih + 1][2 * j],     h1, blo[0], blo[1]);
                    mma_tf32(acc[ih][2 * j + 1],     h0, blo[2], blo[3]);
                    mma_tf32(acc[ih + 1][2 * j + 1], h1, blo[2], blo[3]);
                }
            }
        }
        __syncthreads();

        // refill the stage we just consumed with chunk kc+2
        if (kc + 2 < NCHUNK) {
            const float* a = Ag + (kc + 2) * BK;
            const float* w = Wg + (kc + 2) * BK;
            #pragma unroll
            for (int j = 0; j < 4; j++) {
                CP_ASYNC16(sA + st * STAGEB + j * 16, a + j * 4);
                CP_ASYNC16(sB + st * STAGEB + j * 16, w + j * 4);
            }
        }
        CP_COMMIT();
    }

    // ---- epilogue: write 128x128 tile ----
    const int gid = lane >> 2;
    const int qd  = lane & 3;
    const int m0 = rowBase + wm * 64 + gid;
    const int n0 = colBase + wn * 32 + 2 * qd;
    #pragma unroll
    for (int i = 0; i < 4; i++) {
        #pragma unroll
        for (int jj = 0; jj < 4; jj++) {
            float* p = C + (size_t)(m0 + 16 * i) * N_ + n0 + 8 * jj;
            float2 v01 = make_float2(acc[i][jj][0], acc[i][jj][1]);
            float2 v23 = make_float2(acc[i][jj][2], acc[i][jj][3]);
            *reinterpret_cast<float2*>(p)          = v01;
            *reinterpret_cast<float2*>(p + 8 * N_) = v23;
        }
    }
}

// ======================= K3a: BN partial stats ==============================
__global__ void bn_partial_kernel() {
    int col = blockIdx.x * 256 + threadIdx.x;   // feature m
    int rc  = blockIdx.y;                       // row chunk 0..127 (16 rows each)
    float s = 0.f, sq = 0.f;
    #pragma unroll
    for (int rr = 0; rr < 16; rr++) {
        float h = g_h[(size_t)(rc * 16 + rr) * N_ + col];
        s += h;
        sq = fmaf(h, h, sq);
    }
    g_psum[rc * N_ + col] = s;
    g_psq [rc * N_ + col] = sq;
}

// ======================= K3b: finalize mu/var ===============================
__global__ void bn_final_kernel() {
    int col = blockIdx.x * 256 + threadIdx.x;
    float s = 0.f, sq = 0.f;
    #pragma unroll 8
    for (int rc = 0; rc < 128; rc++) {
        s  += g_psum[rc * N_ + col];
        sq += g_psq [rc * N_ + col];
    }
    float mu = s * (1.0f / TB_);
    g_mu[col]  = mu;
    g_var[col] = sq * (1.0f / TB_) - mu * mu;
}

// ======================= K4: fused BN + 3x LIF + combine ====================
__global__ void fused_lif_kernel(const float* __restrict__ x,
                                 const float* __restrict__ gamma,
                                 const float* __restrict__ beta,
                                 float* __restrict__ out) {
    int idx4 = blockIdx.x * 256 + threadIdx.x;   // float4 index into [B,N]
    int b  = idx4 >> 9;
    int n4 = idx4 & 511;

    float4 mu4  = reinterpret_cast<const float4*>(g_mu)[n4];
    float4 var4 = reinterpret_cast<const float4*>(g_var)[n4];
    float4 ga4  = reinterpret_cast<const float4*>(gamma)[n4];
    float4 be4  = reinterpret_cast<const float4*>(beta)[n4];
    float4 ts4  = reinterpret_cast<const float4*>(g_tsum)[idx4];

    float mu[4]    = {mu4.x, mu4.y, mu4.z, mu4.w};
    float scale[4] = {ga4.x * rsqrtf(var4.x + 1e-5f), ga4.y * rsqrtf(var4.y + 1e-5f),
                      ga4.z * rsqrtf(var4.z + 1e-5f), ga4.w * rsqrtf(var4.w + 1e-5f)};
    float bet[4]   = {be4.x, be4.y, be4.z, be4.w};
    float ts[4]    = {ts4.x, ts4.y, ts4.z, ts4.w};

    float v1[4] = {0, 0, 0, 0}, v2[4] = {0, 0, 0, 0}, v3[4] = {0, 0, 0, 0};
    const float4* h4 = reinterpret_cast<const float4*>(g_h);
    const float4* x4 = reinterpret_cast<const float4*>(x);
    float4* o4 = reinterpret_cast<float4*>(out);

    #pragma unroll
    for (int t = 0; t < T_; t++) {
        size_t off = (size_t)t * (BN_ / 4) + idx4;
        float4 hv = h4[off];
        float4 xv = x4[off];
        float hh[4] = {hv.x, hv.y, hv.z, hv.w};
        float xx[4] = {xv.x, xv.y, xv.z, xv.w};
        float ss = g_ssum[t * B_ + b];
        float res[4];
        #pragma unroll
        for (int j = 0; j < 4; j++) {
            float hn = (hh[j] - mu[j]) * scale[j] + bet[j];
            v1[j] = 0.5f * v1[j] + hn;
            float s1 = (v1[j] >= 1.0f) ? 1.0f : 0.0f;
            v1[j] = (v1[j] >= 1.0f) ? 0.0f : v1[j];
            v2[j] = 0.5f * v2[j] + s1 * ss;
            float s2 = (v2[j] >= 1.0f) ? 1.0f : 0.0f;
            v2[j] = (v2[j] >= 1.0f) ? 0.0f : v2[j];
            v3[j] = 0.5f * v3[j] + s1 * ts[j];
            float s3 = (v3[j] >= 1.0f) ? 1.0f : 0.0f;
            v3[j] = (v3[j] >= 1.0f) ? 0.0f : v3[j];
            res[j] = xx[j] + s2 * s3;
        }
        o4[off] = make_float4(res[0], res[1], res[2], res[3]);
    }
}

// ======================= launch =============================================
extern "C" void kernel_launch(void* const* d_in, const int* in_sizes, int n_in,
                              void* d_out, int out_size) {
    const float* x     = (const float*)d_in[0];   // [T,B,N]
    const float* W     = (const float*)d_in[1];   // [N,N]
    const float* gamma = (const float*)d_in[2];
    const float* beta  = (const float*)d_in[3];
    float* out = (float*)d_out;

    float* h;
    cudaGetSymbolAddress((void**)&h, g_h);

    cudaFuncSetAttribute(gemm_mma_kernel,
                         cudaFuncAttributeMaxDynamicSharedMemorySize, GEMM_SMEM);

    spatial_kernel<<<TB_, 256>>>(x);
    temporal_kernel<<<BN_ / 1024, 256>>>(x);

    dim3 gemmGrid(N_ / 128, TB_ / 128);
    gemm_mma_kernel<<<gemmGrid, 256, GEMM_SMEM>>>(x, W, h);

    dim3 bnGrid(N_ / 256, 128);
    bn_partial_kernel<<<bnGrid, 256>>>();
    bn_final_kernel<<<N_ / 256, 256>>>();

    fused_lif_kernel<<<BN_ / 1024, 256>>>(x, gamma, beta, out);
}

// round 5
// speedup vs baseline: 2.4369x; 1.6770x over previous
#include <cuda_runtime.h>
#include <cuda_fp16.h>
#include <cuda_bf16.h>
#include <cstdint>

// Problem constants
#define T_   16
#define B_   128
#define N_   2048
#define TB_  (T_ * B_)          // 2048 rows
#define BN_  (B_ * N_)          // 262144

// ---------------- scratch (device globals; no allocs allowed) --------------
__device__ float g_h[TB_ * N_];          // GEMM output h [TB, N] (16 MB)
__device__ float g_ssum[T_ * B_];        // spatial_sum [T,B]
__device__ float g_tsum[BN_];            // temporal_sum [B,N]
__device__ float g_psum[128 * N_];       // BN partial sums
__device__ float g_psq[128 * N_];        // BN partial sums of squares
__device__ float g_mu[N_];
__device__ float g_var[N_];

// ======================= helpers ===========================================
__device__ __forceinline__ uint32_t smem_u32(const void* p) {
    uint32_t a;
    asm("{ .reg .u64 t; cvta.to.shared.u64 t, %1; cvt.u32.u64 %0, t; }"
        : "=r"(a) : "l"(p));
    return a;
}

__device__ __forceinline__ void ldsm_x4(uint32_t addr, uint32_t& r0, uint32_t& r1,
                                        uint32_t& r2, uint32_t& r3) {
    asm volatile("ldmatrix.sync.aligned.m8n8.x4.shared.b16 {%0,%1,%2,%3}, [%4];"
                 : "=r"(r0), "=r"(r1), "=r"(r2), "=r"(r3) : "r"(addr));
}

__device__ __forceinline__ void mma_fp16(float* c, const uint32_t* a,
                                         uint32_t b0, uint32_t b1) {
    asm volatile(
        "mma.sync.aligned.m16n8k16.row.col.f32.f16.f16.f32 "
        "{%0,%1,%2,%3}, {%4,%5,%6,%7}, {%8,%9}, {%0,%1,%2,%3};\n"
        : "+f"(c[0]), "+f"(c[1]), "+f"(c[2]), "+f"(c[3])
        : "r"(a[0]), "r"(a[1]), "r"(a[2]), "r"(a[3]), "r"(b0), "r"(b1));
}

// split float4 into fp16 hi / fp16 lo (each packed as 2x half2 -> uint2)
__device__ __forceinline__ void split4h(float4 v, uint2& hi, uint2& lo) {
    __half hx = __float2half_rn(v.x);
    __half hy = __float2half_rn(v.y);
    __half hz = __float2half_rn(v.z);
    __half hw = __float2half_rn(v.w);
    __half lx = __float2half_rn(v.x - __half2float(hx));
    __half ly = __float2half_rn(v.y - __half2float(hy));
    __half lz = __float2half_rn(v.z - __half2float(hz));
    __half lw = __float2half_rn(v.w - __half2float(hw));
    __half2 h01 = __halves2half2(hx, hy);
    __half2 h23 = __halves2half2(hz, hw);
    __half2 l01 = __halves2half2(lx, ly);
    __half2 l23 = __halves2half2(lz, lw);
    hi.x = *reinterpret_cast<uint32_t*>(&h01);
    hi.y = *reinterpret_cast<uint32_t*>(&h23);
    lo.x = *reinterpret_cast<uint32_t*>(&l01);
    lo.y = *reinterpret_cast<uint32_t*>(&l23);
}

// ======================= K1a: spatial_sum ===================================
__global__ void spatial_kernel(const float* __restrict__ x) {
    int row = blockIdx.x;                       // t*B + b
    const float4* xr = reinterpret_cast<const float4*>(x + (size_t)row * N_);
    float s = 0.f;
    #pragma unroll
    for (int i = 0; i < 2; i++) {
        float4 v = xr[threadIdx.x + i * 256];
        s += v.x + v.y + v.z + v.w;
    }
    __shared__ float red[8];
    for (int off = 16; off > 0; off >>= 1)
        s += __shfl_down_sync(0xffffffffu, s, off);
    if ((threadIdx.x & 31) == 0) red[threadIdx.x >> 5] = s;
    __syncthreads();
    if (threadIdx.x < 8) {
        s = red[threadIdx.x];
        for (int off = 4; off > 0; off >>= 1)
            s += __shfl_down_sync(0xffu, s, off);
        if (threadIdx.x == 0) g_ssum[row] = s;
    }
}

// ======================= K1b: temporal_sum ==================================
__global__ void temporal_kernel(const float* __restrict__ x) {
    int idx4 = blockIdx.x * 256 + threadIdx.x;   // float4 index into [B,N]
    const float4* x4 = reinterpret_cast<const float4*>(x);
    float4 s = make_float4(0.f, 0.f, 0.f, 0.f);
    #pragma unroll
    for (int t = 0; t < T_; t++) {
        float4 v = x4[(size_t)t * (BN_ / 4) + idx4];
        s.x += v.x; s.y += v.y; s.z += v.z; s.w += v.w;
    }
    reinterpret_cast<float4*>(g_tsum)[idx4] = s;
}

// ======================= K2: mma.sync fp16x3 GEMM ===========================
// h[r,m] = sum_k x[r,k] * W[m,k].
// CTA tile 128(M) x 128(N) x 16(K), 256 threads = 8 warps (2x4), warp 64x32.
// fp16 split: hi = rn_f16(x), lo = rn_f16(x - hi); keep hh + hl + lh.
// m16n8k16 MMAs: half the instruction count of tf32 m16n8k8 at same precision.
#define BK      16
#define HPITCH  24                      // halfs per smem row (16 + 8 pad)
#define HTILE   (128 * HPITCH)          // halfs per tile
#define HTILEB  (HTILE * 2)             // 6144 bytes
#define STAGEB  (4 * HTILEB)            // A_hi, A_lo, B_hi, B_lo: 24576 B
#define GEMM_SMEM (2 * STAGEB)          // 49152 bytes

__global__ __launch_bounds__(256, 2)
void gemm_mma_kernel(const float* __restrict__ A, const float* __restrict__ W,
                     float* __restrict__ C) {
    extern __shared__ char smc[];
    const uint32_t sbase = smem_u32(smc);
    const int tid  = threadIdx.x;
    const int wid  = tid >> 5;
    const int lane = tid & 31;
    const int wm = wid >> 2;            // 0..1 -> 64-row slab
    const int wn = wid & 3;             // 0..3 -> 32-col slab
    const int rowBase = blockIdx.y * 128;
    const int colBase = blockIdx.x * 128;

    float acc[4][4][4];
    #pragma unroll
    for (int i = 0; i < 4; i++)
        #pragma unroll
        for (int j = 0; j < 4; j++)
            #pragma unroll
            for (int c = 0; c < 4; c++) acc[i][j][c] = 0.f;

    // ---- gmem loader: 256 threads cover 128 rows x 16 floats (2 f4/thread) --
    const int lrow = tid >> 1;                  // 0..127
    const int lq   = (tid & 1) * 8;             // float offset within row
    const float* Ag = A + (size_t)(rowBase + lrow) * N_ + lq;
    const float* Wg = W + (size_t)(colBase + lrow) * N_ + lq;
    const uint32_t sOffB = (uint32_t)((lrow * HPITCH + lq) * 2);  // bytes

    // ---- ldmatrix per-lane byte offsets ----
    const uint32_t aLane = (uint32_t)((((lane & 15) * HPITCH) + (lane >> 4) * 8) * 2);
    const uint32_t bLane = (uint32_t)(((((lane & 7) + ((lane >> 4) & 1) * 8) * HPITCH)
                                       + ((lane >> 3) & 1) * 8) * 2);
    const uint32_t aBase = sbase + (uint32_t)((wm * 64) * HPITCH * 2) + aLane;
    const uint32_t bBase = sbase + 2 * HTILEB + (uint32_t)((wn * 32) * HPITCH * 2) + bLane;

    // ---- preload chunk 0 into stage 0 ----
    {
        float4 va0 = *reinterpret_cast<const float4*>(Ag);
        float4 va1 = *reinterpret_cast<const float4*>(Ag + 4);
        float4 vb0 = *reinterpret_cast<const float4*>(Wg);
        float4 vb1 = *reinterpret_cast<const float4*>(Wg + 4);
        uint2 hi, lo;
        char* st = smc;
        split4h(va0, hi, lo);
        *reinterpret_cast<uint2*>(st + sOffB)              = hi;
        *reinterpret_cast<uint2*>(st + HTILEB + sOffB)     = lo;
        split4h(va1, hi, lo);
        *reinterpret_cast<uint2*>(st + sOffB + 8)          = hi;
        *reinterpret_cast<uint2*>(st + HTILEB + sOffB + 8) = lo;
        split4h(vb0, hi, lo);
        *reinterpret_cast<uint2*>(st + 2 * HTILEB + sOffB)     = hi;
        *reinterpret_cast<uint2*>(st + 3 * HTILEB + sOffB)     = lo;
        split4h(vb1, hi, lo);
        *reinterpret_cast<uint2*>(st + 2 * HTILEB + sOffB + 8) = hi;
        *reinterpret_cast<uint2*>(st + 3 * HTILEB + sOffB + 8) = lo;
    }
    __syncthreads();

    const int NCHUNK = N_ / BK;          // 128
    #pragma unroll 1
    for (int kc = 0; kc < NCHUNK; kc++) {
        const int st = kc & 1;

        // prefetch next chunk into registers
        float4 va0, va1, vb0, vb1;
        const bool pf = (kc + 1 < NCHUNK);
        if (pf) {
            const float* Agk = Ag + (kc + 1) * BK;
            const float* Wgk = Wg + (kc + 1) * BK;
            va0 = *reinterpret_cast<const float4*>(Agk);
            va1 = *reinterpret_cast<const float4*>(Agk + 4);
            vb0 = *reinterpret_cast<const float4*>(Wgk);
            vb1 = *reinterpret_cast<const float4*>(Wgk + 4);
        }

        // ---- compute: one k16 step, products hh + lh + hl ----
        const uint32_t aS = aBase + st * STAGEB;
        const uint32_t bS = bBase + st * STAGEB;

        uint32_t bh[2][4], bl[2][4];
        #pragma unroll
        for (int jp = 0; jp < 2; jp++) {
            ldsm_x4(bS + jp * (16 * HPITCH * 2),
                    bh[jp][0], bh[jp][1], bh[jp][2], bh[jp][3]);
            ldsm_x4(bS + HTILEB + jp * (16 * HPITCH * 2),
                    bl[jp][0], bl[jp][1], bl[jp][2], bl[jp][3]);
        }
        #pragma unroll
        for (int i = 0; i < 4; i++) {
            uint32_t ah[4], al[4];
            ldsm_x4(aS + i * (16 * HPITCH * 2), ah[0], ah[1], ah[2], ah[3]);
            ldsm_x4(aS + HTILEB + i * (16 * HPITCH * 2), al[0], al[1], al[2], al[3]);
            // hh
            #pragma unroll
            for (int j = 0; j < 4; j++)
                mma_fp16(acc[i][j], ah, bh[j >> 1][(j & 1) * 2], bh[j >> 1][(j & 1) * 2 + 1]);
            // lh
            #pragma unroll
            for (int j = 0; j < 4; j++)
                mma_fp16(acc[i][j], al, bh[j >> 1][(j & 1) * 2], bh[j >> 1][(j & 1) * 2 + 1]);
            // hl
            #pragma unroll
            for (int j = 0; j < 4; j++)
                mma_fp16(acc[i][j], ah, bl[j >> 1][(j & 1) * 2], bl[j >> 1][(j & 1) * 2 + 1]);
        }

        // ---- split + STS next chunk into the other stage ----
        if (pf) {
            char* stn = smc + (st ^ 1) * STAGEB;
            uint2 hi, lo;
            split4h(va0, hi, lo);
            *reinterpret_cast<uint2*>(stn + sOffB)              = hi;
            *reinterpret_cast<uint2*>(stn + HTILEB + sOffB)     = lo;
            split4h(va1, hi, lo);
            *reinterpret_cast<uint2*>(stn + sOffB + 8)          = hi;
            *reinterpret_cast<uint2*>(stn + HTILEB + sOffB + 8) = lo;
            split4h(vb0, hi, lo);
            *reinterpret_cast<uint2*>(stn + 2 * HTILEB + sOffB)     = hi;
            *reinterpret_cast<uint2*>(stn + 3 * HTILEB + sOffB)     = lo;
            split4h(vb1, hi, lo);
            *reinterpret_cast<uint2*>(stn + 2 * HTILEB + sOffB + 8) = hi;
            *reinterpret_cast<uint2*>(stn + 3 * HTILEB + sOffB + 8) = lo;
        }
        __syncthreads();
    }

    // ---- epilogue: write 128x128 tile ----
    const int gid = lane >> 2;
    const int qd  = lane & 3;
    const int m0 = rowBase + wm * 64 + gid;
    const int n0 = colBase + wn * 32 + 2 * qd;
    #pragma unroll
    for (int i = 0; i < 4; i++) {
        #pragma unroll
        for (int jj = 0; jj < 4; jj++) {
            float* p = C + (size_t)(m0 + 16 * i) * N_ + n0 + 8 * jj;
            float2 v01 = make_float2(acc[i][jj][0], acc[i][jj][1]);
            float2 v23 = make_float2(acc[i][jj][2], acc[i][jj][3]);
            *reinterpret_cast<float2*>(p)          = v01;
            *reinterpret_cast<float2*>(p + 8 * N_) = v23;
        }
    }
}

// ======================= K3a: BN partial stats ==============================
__global__ void bn_partial_kernel() {
    int col = blockIdx.x * 256 + threadIdx.x;   // feature m
    int rc  = blockIdx.y;                       // row chunk 0..127 (16 rows each)
    float s = 0.f, sq = 0.f;
    #pragma unroll
    for (int rr = 0; rr < 16; rr++) {
        float h = g_h[(size_t)(rc * 16 + rr) * N_ + col];
        s += h;
        sq = fmaf(h, h, sq);
    }
    g_psum[rc * N_ + col] = s;
    g_psq [rc * N_ + col] = sq;
}

// ======================= K3b: finalize mu/var ===============================
__global__ void bn_final_kernel() {
    int col = blockIdx.x * 256 + threadIdx.x;
    float s = 0.f, sq = 0.f;
    #pragma unroll 8
    for (int rc = 0; rc < 128; rc++) {
        s  += g_psum[rc * N_ + col];
        sq += g_psq [rc * N_ + col];
    }
    float mu = s * (1.0f / TB_);
    g_mu[col]  = mu;
    g_var[col] = sq * (1.0f / TB_) - mu * mu;
}

// ======================= K4: fused BN + 3x LIF + combine ====================
__global__ void fused_lif_kernel(const float* __restrict__ x,
                                 const float* __restrict__ gamma,
                                 const float* __restrict__ beta,
                                 float* __restrict__ out) {
    int idx4 = blockIdx.x * 256 + threadIdx.x;   // float4 index into [B,N]
    int b  = idx4 >> 9;
    int n4 = idx4 & 511;

    float4 mu4  = reinterpret_cast<const float4*>(g_mu)[n4];
    float4 var4 = reinterpret_cast<const float4*>(g_var)[n4];
    float4 ga4  = reinterpret_cast<const float4*>(gamma)[n4];
    float4 be4  = reinterpret_cast<const float4*>(beta)[n4];
    float4 ts4  = reinterpret_cast<const float4*>(g_tsum)[idx4];

    float mu[4]    = {mu4.x, mu4.y, mu4.z, mu4.w};
    float scale[4] = {ga4.x * rsqrtf(var4.x + 1e-5f), ga4.y * rsqrtf(var4.y + 1e-5f),
                      ga4.z * rsqrtf(var4.z + 1e-5f), ga4.w * rsqrtf(var4.w + 1e-5f)};
    float bet[4]   = {be4.x, be4.y, be4.z, be4.w};
    float ts[4]    = {ts4.x, ts4.y, ts4.z, ts4.w};

    float v1[4] = {0, 0, 0, 0}, v2[4] = {0, 0, 0, 0}, v3[4] = {0, 0, 0, 0};
    const float4* h4 = reinterpret_cast<const float4*>(g_h);
    const float4* x4 = reinterpret_cast<const float4*>(x);
    float4* o4 = reinterpret_cast<float4*>(out);

    #pragma unroll
    for (int t = 0; t < T_; t++) {
        size_t off = (size_t)t * (BN_ / 4) + idx4;
        float4 hv = h4[off];
        float4 xv = x4[off];
        float hh[4] = {hv.x, hv.y, hv.z, hv.w};
        float xx[4] = {xv.x, xv.y, xv.z, xv.w};
        float ss = g_ssum[t * B_ + b];
        float res[4];
        #pragma unroll
        for (int j = 0; j < 4; j++) {
            float hn = (hh[j] - mu[j]) * scale[j] + bet[j];
            v1[j] = 0.5f * v1[j] + hn;
            float s1 = (v1[j] >= 1.0f) ? 1.0f : 0.0f;
            v1[j] = (v1[j] >= 1.0f) ? 0.0f : v1[j];
            v2[j] = 0.5f * v2[j] + s1 * ss;
            float s2 = (v2[j] >= 1.0f) ? 1.0f : 0.0f;
            v2[j] = (v2[j] >= 1.0f) ? 0.0f : v2[j];
            v3[j] = 0.5f * v3[j] + s1 * ts[j];
            float s3 = (v3[j] >= 1.0f) ? 1.0f : 0.0f;
            v3[j] = (v3[j] >= 1.0f) ? 0.0f : v3[j];
            res[j] = xx[j] + s2 * s3;
        }
        o4[off] = make_float4(res[0], res[1], res[2], res[3]);
    }
}

// ======================= launch =============================================
extern "C" void kernel_launch(void* const* d_in, const int* in_sizes, int n_in,
                              void* d_out, int out_size) {
    const float* x     = (const float*)d_in[0];   // [T,B,N]
    const float* W     = (const float*)d_in[1];   // [N,N]
    const float* gamma = (const float*)d_in[2];
    const float* beta  = (const float*)d_in[3];
    float* out = (float*)d_out;

    float* h;
    cudaGetSymbolAddress((void**)&h, g_h);

    cudaFuncSetAttribute(gemm_mma_kernel,
                         cudaFuncAttributeMaxDynamicSharedMemorySize, GEMM_SMEM);

    spatial_kernel<<<TB_, 256>>>(x);
    temporal_kernel<<<BN_ / 1024, 256>>>(x);

    dim3 gemmGrid(N_ / 128, TB_ / 128);
    gemm_mma_kernel<<<gemmGrid, 256, GEMM_SMEM>>>(x, W, h);

    dim3 bnGrid(N_ / 256, 128);
    bn_partial_kernel<<<bnGrid, 256>>>();
    bn_final_kernel<<<N_ / 256, 256>>>();

    fused_lif_kernel<<<BN_ / 1024, 256>>>(x, gamma, beta, out);
}

// round 6
// speedup vs baseline: 2.4856x; 1.0200x over previous
#include <cuda_runtime.h>
#include <cuda_fp16.h>
#include <cuda_bf16.h>
#include <cstdint>

// Problem constants
#define T_   16
#define B_   128
#define N_   2048
#define TB_  (T_ * B_)          // 2048 rows
#define BN_  (B_ * N_)          // 262144

// ---------------- scratch (device globals; no allocs allowed) --------------
__device__ float  g_h[TB_ * N_];         // GEMM output h [TB, N] (16 MB)
__device__ __half g_ah[TB_ * N_];        // A = x  fp16 hi plane (8 MB)
__device__ __half g_al[TB_ * N_];        // A lo plane
__device__ __half g_wh[N_ * N_];         // W hi plane
__device__ __half g_wl[N_ * N_];         // W lo plane
__device__ float  g_ssum[T_ * B_];       // spatial_sum [T,B]
__device__ float  g_tsum[BN_];           // temporal_sum [B,N]
__device__ float  g_colsum[N_];          // BN column sums (atomic)
__device__ float  g_colsq[N_];           // BN column sums of squares
__device__ float  g_mu[N_];
__device__ float  g_var[N_];

// ======================= helpers ===========================================
__device__ __forceinline__ uint32_t smem_u32(const void* p) {
    uint32_t a;
    asm("{ .reg .u64 t; cvta.to.shared.u64 t, %1; cvt.u32.u64 %0, t; }"
        : "=r"(a) : "l"(p));
    return a;
}

__device__ __forceinline__ void ldsm_x4(uint32_t addr, uint32_t& r0, uint32_t& r1,
                                        uint32_t& r2, uint32_t& r3) {
    asm volatile("ldmatrix.sync.aligned.m8n8.x4.shared.b16 {%0,%1,%2,%3}, [%4];"
                 : "=r"(r0), "=r"(r1), "=r"(r2), "=r"(r3) : "r"(addr));
}

__device__ __forceinline__ void mma_fp16(float* c, const uint32_t* a,
                                         uint32_t b0, uint32_t b1) {
    asm volatile(
        "mma.sync.aligned.m16n8k16.row.col.f32.f16.f16.f32 "
        "{%0,%1,%2,%3}, {%4,%5,%6,%7}, {%8,%9}, {%0,%1,%2,%3};\n"
        : "+f"(c[0]), "+f"(c[1]), "+f"(c[2]), "+f"(c[3])
        : "r"(a[0]), "r"(a[1]), "r"(a[2]), "r"(a[3]), "r"(b0), "r"(b1));
}

#define CP_ASYNC16(dst, src) \
    asm volatile("cp.async.ca.shared.global [%0], [%1], 16;" :: "r"(dst), "l"(src))
#define CP_COMMIT() asm volatile("cp.async.commit_group;" ::: "memory")
#define CP_WAIT1()  asm volatile("cp.async.wait_group 1;" ::: "memory")

// split float4 into fp16 hi / fp16 lo (each packed as 2x half2 -> uint2)
__device__ __forceinline__ void split4h(float4 v, uint2& hi, uint2& lo) {
    __half hx = __float2half_rn(v.x);
    __half hy = __float2half_rn(v.y);
    __half hz = __float2half_rn(v.z);
    __half hw = __float2half_rn(v.w);
    __half lx = __float2half_rn(v.x - __half2float(hx));
    __half ly = __float2half_rn(v.y - __half2float(hy));
    __half lz = __float2half_rn(v.z - __half2float(hz));
    __half lw = __float2half_rn(v.w - __half2float(hw));
    __half2 h01 = __halves2half2(hx, hy);
    __half2 h23 = __halves2half2(hz, hw);
    __half2 l01 = __halves2half2(lx, ly);
    __half2 l23 = __halves2half2(lz, lw);
    hi.x = *reinterpret_cast<uint32_t*>(&h01);
    hi.y = *reinterpret_cast<uint32_t*>(&h23);
    lo.x = *reinterpret_cast<uint32_t*>(&l01);
    lo.y = *reinterpret_cast<uint32_t*>(&l23);
}

// ======================= K0: zero BN accumulators ===========================
__global__ void zero_kernel() {
    int i = blockIdx.x * 256 + threadIdx.x;
    g_colsum[i] = 0.f;
    g_colsq[i]  = 0.f;
}

// ======================= K1a: spatial_sum ===================================
__global__ void spatial_kernel(const float* __restrict__ x) {
    int row = blockIdx.x;                       // t*B + b
    const float4* xr = reinterpret_cast<const float4*>(x + (size_t)row * N_);
    float s = 0.f;
    #pragma unroll
    for (int i = 0; i < 2; i++) {
        float4 v = xr[threadIdx.x + i * 256];
        s += v.x + v.y + v.z + v.w;
    }
    __shared__ float red[8];
    for (int off = 16; off > 0; off >>= 1)
        s += __shfl_down_sync(0xffffffffu, s, off);
    if ((threadIdx.x & 31) == 0) red[threadIdx.x >> 5] = s;
    __syncthreads();
    if (threadIdx.x < 8) {
        s = red[threadIdx.x];
        for (int off = 4; off > 0; off >>= 1)
            s += __shfl_down_sync(0xffu, s, off);
        if (threadIdx.x == 0) g_ssum[row] = s;
    }
}

// ======================= K1b: x split + temporal_sum ========================
__global__ void xsplit_kernel(const float* __restrict__ x) {
    int idx4 = blockIdx.x * 256 + threadIdx.x;   // float4 index into [B,N]
    const float4* x4 = reinterpret_cast<const float4*>(x);
    uint2* ah2 = reinterpret_cast<uint2*>(g_ah);
    uint2* al2 = reinterpret_cast<uint2*>(g_al);
    float4 s = make_float4(0.f, 0.f, 0.f, 0.f);
    #pragma unroll
    for (int t = 0; t < T_; t++) {
        size_t off = (size_t)t * (BN_ / 4) + idx4;
        float4 v = x4[off];
        s.x += v.x; s.y += v.y; s.z += v.z; s.w += v.w;
        uint2 hi, lo;
        split4h(v, hi, lo);
        ah2[off] = hi;
        al2[off] = lo;
    }
    reinterpret_cast<float4*>(g_tsum)[idx4] = s;
}

// ======================= K1c: W split =======================================
__global__ void wsplit_kernel(const float* __restrict__ W) {
    int idx4 = blockIdx.x * 256 + threadIdx.x;   // float4 index into [N,N]
    const float4* w4 = reinterpret_cast<const float4*>(W);
    uint2* wh2 = reinterpret_cast<uint2*>(g_wh);
    uint2* wl2 = reinterpret_cast<uint2*>(g_wl);
    float4 v = w4[idx4];
    uint2 hi, lo;
    split4h(v, hi, lo);
    wh2[idx4] = hi;
    wl2[idx4] = lo;
}

// ======================= K2: mma.sync fp16x3 GEMM (pre-split) ===============
// h[r,m] = sum_k x[r,k] * W[m,k].
// CTA tile 128(M) x 128(N) x 32(K), 256 threads = 8 warps (2x4), warp 64x32.
// fp16 planes pre-split in gmem; hot loop is pure cp.async + LDSM + MMA.
// Epilogue fuses BN column statistics via shfl-reduce + atomics.
#define BK      32
#define HPITCH  40                      // halfs per smem row (32 + 8 pad)
#define PLANEB  (128 * HPITCH * 2)      // 10240 bytes per plane
#define STAGEB  (4 * PLANEB)            // A_hi, A_lo, B_hi, B_lo: 40960 B
#define GEMM_SMEM (2 * STAGEB)          // 81920 bytes

__global__ __launch_bounds__(256, 2)
void gemm_mma_kernel(float* __restrict__ C) {
    extern __shared__ char smc[];
    const uint32_t sbase = smem_u32(smc);
    const int tid  = threadIdx.x;
    const int wid  = tid >> 5;
    const int lane = tid & 31;
    const int wm = wid >> 2;            // 0..1 -> 64-row slab
    const int wn = wid & 3;             // 0..3 -> 32-col slab
    const int rowBase = blockIdx.y * 128;
    const int colBase = blockIdx.x * 128;

    float acc[4][4][4];
    #pragma unroll
    for (int i = 0; i < 4; i++)
        #pragma unroll
        for (int j = 0; j < 4; j++)
            #pragma unroll
            for (int c = 0; c < 4; c++) acc[i][j][c] = 0.f;

    // ---- cp.async loader: thread -> (row, 16-half part) ----
    const int lrow = tid >> 1;                  // 0..127
    const int part = (tid & 1) * 16;            // half offset within row
    const __half* pAh = g_ah + (size_t)(rowBase + lrow) * N_ + part;
    const __half* pAl = g_al + (size_t)(rowBase + lrow) * N_ + part;
    const __half* pBh = g_wh + (size_t)(colBase + lrow) * N_ + part;
    const __half* pBl = g_wl + (size_t)(colBase + lrow) * N_ + part;
    const uint32_t dRow = (uint32_t)((lrow * HPITCH + part) * 2);

    // ---- ldmatrix per-lane byte offsets ----
    const uint32_t aLane = (uint32_t)((((lane & 15) * HPITCH) + (lane >> 4) * 8) * 2);
    const uint32_t bLane = (uint32_t)(((((lane & 7) + ((lane >> 4) & 1) * 8) * HPITCH)
                                       + ((lane >> 3) & 1) * 8) * 2);
    const uint32_t aBase = sbase + (uint32_t)((wm * 64) * HPITCH * 2) + aLane;
    const uint32_t bBase = sbase + 2 * PLANEB + (uint32_t)((wn * 32) * HPITCH * 2) + bLane;

    // ---- prologue: load chunks 0,1 ----
    #pragma unroll
    for (int s = 0; s < 2; s++) {
        const uint32_t d = sbase + s * STAGEB + dRow;
        const int ko = s * BK;
        CP_ASYNC16(d,                       pAh + ko);
        CP_ASYNC16(d + 16,                  pAh + ko + 8);
        CP_ASYNC16(d + PLANEB,              pAl + ko);
        CP_ASYNC16(d + PLANEB + 16,         pAl + ko + 8);
        CP_ASYNC16(d + 2 * PLANEB,          pBh + ko);
        CP_ASYNC16(d + 2 * PLANEB + 16,     pBh + ko + 8);
        CP_ASYNC16(d + 3 * PLANEB,          pBl + ko);
        CP_ASYNC16(d + 3 * PLANEB + 16,     pBl + ko + 8);
        CP_COMMIT();
    }

    const int NCHUNK = N_ / BK;          // 64
    #pragma unroll 1
    for (int kc = 0; kc < NCHUNK; kc++) {
        const int st = kc & 1;
        CP_WAIT1();
        __syncthreads();

        const uint32_t aS = aBase + st * STAGEB;
        const uint32_t bS = bBase + st * STAGEB;

        #pragma unroll
        for (int ks = 0; ks < 2; ks++) {
            const uint32_t kb = ks * 32;   // 16 halfs = 32 bytes
            uint32_t bh[2][4], bl[2][4];
            #pragma unroll
            for (int jp = 0; jp < 2; jp++) {
                ldsm_x4(bS + kb + jp * (16 * HPITCH * 2),
                        bh[jp][0], bh[jp][1], bh[jp][2], bh[jp][3]);
                ldsm_x4(bS + PLANEB + kb + jp * (16 * HPITCH * 2),
                        bl[jp][0], bl[jp][1], bl[jp][2], bl[jp][3]);
            }
            #pragma unroll
            for (int i = 0; i < 4; i++) {
                uint32_t ah[4], al[4];
                ldsm_x4(aS + kb + i * (16 * HPITCH * 2), ah[0], ah[1], ah[2], ah[3]);
                ldsm_x4(aS + PLANEB + kb + i * (16 * HPITCH * 2), al[0], al[1], al[2], al[3]);
                #pragma unroll
                for (int j = 0; j < 4; j++)
                    mma_fp16(acc[i][j], ah, bh[j >> 1][(j & 1) * 2], bh[j >> 1][(j & 1) * 2 + 1]);
                #pragma unroll
                for (int j = 0; j < 4; j++)
                    mma_fp16(acc[i][j], al, bh[j >> 1][(j & 1) * 2], bh[j >> 1][(j & 1) * 2 + 1]);
                #pragma unroll
                for (int j = 0; j < 4; j++)
                    mma_fp16(acc[i][j], ah, bl[j >> 1][(j & 1) * 2], bl[j >> 1][(j & 1) * 2 + 1]);
            }
        }
        __syncthreads();

        // refill the consumed stage with chunk kc+2
        if (kc + 2 < NCHUNK) {
            const uint32_t d = sbase + st * STAGEB + dRow;
            const int ko = (kc + 2) * BK;
            CP_ASYNC16(d,                       pAh + ko);
            CP_ASYNC16(d + 16,                  pAh + ko + 8);
            CP_ASYNC16(d + PLANEB,              pAl + ko);
            CP_ASYNC16(d + PLANEB + 16,         pAl + ko + 8);
            CP_ASYNC16(d + 2 * PLANEB,          pBh + ko);
            CP_ASYNC16(d + 2 * PLANEB + 16,     pBh + ko + 8);
            CP_ASYNC16(d + 3 * PLANEB,          pBl + ko);
            CP_ASYNC16(d + 3 * PLANEB + 16,     pBl + ko + 8);
        }
        CP_COMMIT();
    }

    // ---- epilogue: write 128x128 tile + fused BN column stats ----
    const int gid = lane >> 2;
    const int qd  = lane & 3;
    const int m0 = rowBase + wm * 64 + gid;
    const int n0 = colBase + wn * 32 + 2 * qd;
    #pragma unroll
    for (int i = 0; i < 4; i++) {
        #pragma unroll
        for (int jj = 0; jj < 4; jj++) {
            float* p = C + (size_t)(m0 + 16 * i) * N_ + n0 + 8 * jj;
            float2 v01 = make_float2(acc[i][jj][0], acc[i][jj][1]);
            float2 v23 = make_float2(acc[i][jj][2], acc[i][jj][3]);
            *reinterpret_cast<float2*>(p)          = v01;
            *reinterpret_cast<float2*>(p + 8 * N_) = v23;
        }
    }

    // column sums / sums-of-squares over this warp's 64 rows
    float s[4][2], q[4][2];
    #pragma unroll
    for (int j = 0; j < 4; j++) {
        s[j][0] = s[j][1] = q[j][0] = q[j][1] = 0.f;
        #pragma unroll
        for (int i = 0; i < 4; i++) {
            s[j][0] += acc[i][j][0] + acc[i][j][2];
            s[j][1] += acc[i][j][1] + acc[i][j][3];
            q[j][0] += acc[i][j][0] * acc[i][j][0] + acc[i][j][2] * acc[i][j][2];
            q[j][1] += acc[i][j][1] * acc[i][j][1] + acc[i][j][3] * acc[i][j][3];
        }
    }
    #pragma unroll
    for (int j = 0; j < 4; j++)
        #pragma unroll
        for (int c = 0; c < 2; c++) {
            #pragma unroll
            for (int off = 16; off >= 4; off >>= 1) {
                s[j][c] += __shfl_down_sync(0xffffffffu, s[j][c], off);
                q[j][c] += __shfl_down_sync(0xffffffffu, q[j][c], off);
            }
        }
    if (lane < 4) {
        #pragma unroll
        for (int j = 0; j < 4; j++)
            #pragma unroll
            for (int c = 0; c < 2; c++) {
                int col = colBase + wn * 32 + 2 * lane + 8 * j + c;
                atomicAdd(&g_colsum[col], s[j][c]);
                atomicAdd(&g_colsq[col],  q[j][c]);
            }
    }
}

// ======================= K3: finalize mu/var ================================
__global__ void bn_final_kernel() {
    int col = blockIdx.x * 256 + threadIdx.x;
    float mu = g_colsum[col] * (1.0f / TB_);
    g_mu[col]  = mu;
    g_var[col] = g_colsq[col] * (1.0f / TB_) - mu * mu;
}

// ======================= K4: fused BN + 3x LIF + combine ====================
__global__ void fused_lif_kernel(const float* __restrict__ x,
                                 const float* __restrict__ gamma,
                                 const float* __restrict__ beta,
                                 float* __restrict__ out) {
    int idx4 = blockIdx.x * 256 + threadIdx.x;   // float4 index into [B,N]
    int b  = idx4 >> 9;
    int n4 = idx4 & 511;

    float4 mu4  = reinterpret_cast<const float4*>(g_mu)[n4];
    float4 var4 = reinterpret_cast<const float4*>(g_var)[n4];
    float4 ga4  = reinterpret_cast<const float4*>(gamma)[n4];
    float4 be4  = reinterpret_cast<const float4*>(beta)[n4];
    float4 ts4  = reinterpret_cast<const float4*>(g_tsum)[idx4];

    float mu[4]    = {mu4.x, mu4.y, mu4.z, mu4.w};
    float scale[4] = {ga4.x * rsqrtf(var4.x + 1e-5f), ga4.y * rsqrtf(var4.y + 1e-5f),
                      ga4.z * rsqrtf(var4.z + 1e-5f), ga4.w * rsqrtf(var4.w + 1e-5f)};
    float bet[4]   = {be4.x, be4.y, be4.z, be4.w};
    float ts[4]    = {ts4.x, ts4.y, ts4.z, ts4.w};

    float v1[4] = {0, 0, 0, 0}, v2[4] = {0, 0, 0, 0}, v3[4] = {0, 0, 0, 0};
    const float4* h4 = reinterpret_cast<const float4*>(g_h);
    const float4* x4 = reinterpret_cast<const float4*>(x);
    float4* o4 = reinterpret_cast<float4*>(out);

    #pragma unroll
    for (int t = 0; t < T_; t++) {
        size_t off = (size_t)t * (BN_ / 4) + idx4;
        float4 hv = h4[off];
        float4 xv = x4[off];
        float hh[4] = {hv.x, hv.y, hv.z, hv.w};
        float xx[4] = {xv.x, xv.y, xv.z, xv.w};
        float ss = g_ssum[t * B_ + b];
        float res[4];
        #pragma unroll
        for (int j = 0; j < 4; j++) {
            float hn = (hh[j] - mu[j]) * scale[j] + bet[j];
            v1[j] = 0.5f * v1[j] + hn;
            float s1 = (v1[j] >= 1.0f) ? 1.0f : 0.0f;
            v1[j] = (v1[j] >= 1.0f) ? 0.0f : v1[j];
            v2[j] = 0.5f * v2[j] + s1 * ss;
            float s2 = (v2[j] >= 1.0f) ? 1.0f : 0.0f;
            v2[j] = (v2[j] >= 1.0f) ? 0.0f : v2[j];
            v3[j] = 0.5f * v3[j] + s1 * ts[j];
            float s3 = (v3[j] >= 1.0f) ? 1.0f : 0.0f;
            v3[j] = (v3[j] >= 1.0f) ? 0.0f : v3[j];
            res[j] = xx[j] + s2 * s3;
        }
        o4[off] = make_float4(res[0], res[1], res[2], res[3]);
    }
}

// ======================= launch =============================================
extern "C" void kernel_launch(void* const* d_in, const int* in_sizes, int n_in,
                              void* d_out, int out_size) {
    const float* x     = (const float*)d_in[0];   // [T,B,N]
    const float* W     = (const float*)d_in[1];   // [N,N]
    const float* gamma = (const float*)d_in[2];
    const float* beta  = (const float*)d_in[3];
    float* out = (float*)d_out;

    float* h;
    cudaGetSymbolAddress((void**)&h, g_h);

    cudaFuncSetAttribute(gemm_mma_kernel,
                         cudaFuncAttributeMaxDynamicSharedMemorySize, GEMM_SMEM);

    zero_kernel<<<N_ / 256, 256>>>();
    xsplit_kernel<<<BN_ / 1024, 256>>>(x);
    wsplit_kernel<<<(N_ * N_) / 1024, 256>>>(W);
    spatial_kernel<<<TB_, 256>>>(x);

    dim3 gemmGrid(N_ / 128, TB_ / 128);
    gemm_mma_kernel<<<gemmGrid, 256, GEMM_SMEM>>>(h);

    bn_final_kernel<<<N_ / 256, 256>>>();
    fused_lif_kernel<<<BN_ / 1024, 256>>>(x, gamma, beta, out);
}

// round 7
// speedup vs baseline: 2.6253x; 1.0562x over previous
#include <cuda_runtime.h>
#include <cuda_fp16.h>
#include <cuda_bf16.h>
#include <cstdint>

// Problem constants
#define T_   16
#define B_   128
#define N_   2048
#define TB_  (T_ * B_)          // 2048 rows
#define BN_  (B_ * N_)          // 262144

// ---------------- scratch (device globals; no allocs allowed) --------------
__device__ float  g_h[TB_ * N_];         // GEMM output h [TB, N] (16 MB)
__device__ __half g_ah[TB_ * N_];        // A = x  fp16 hi plane (8 MB)
__device__ __half g_al[TB_ * N_];        // A lo plane
__device__ __half g_wh[N_ * N_];         // W hi plane
__device__ __half g_wl[N_ * N_];         // W lo plane
__device__ float  g_sspart[T_ * 256];    // spatial_sum partials [T][256] (2/b)
__device__ float  g_tsum[BN_];           // temporal_sum [B,N]
__device__ float  g_colsum[N_];          // BN column sums (atomic)
__device__ float  g_colsq[N_];           // BN column sums of squares

// ======================= helpers ===========================================
__device__ __forceinline__ uint32_t smem_u32(const void* p) {
    uint32_t a;
    asm("{ .reg .u64 t; cvta.to.shared.u64 t, %1; cvt.u32.u64 %0, t; }"
        : "=r"(a) : "l"(p));
    return a;
}

__device__ __forceinline__ void ldsm_x4(uint32_t addr, uint32_t& r0, uint32_t& r1,
                                        uint32_t& r2, uint32_t& r3) {
    asm volatile("ldmatrix.sync.aligned.m8n8.x4.shared.b16 {%0,%1,%2,%3}, [%4];"
                 : "=r"(r0), "=r"(r1), "=r"(r2), "=r"(r3) : "r"(addr));
}

__device__ __forceinline__ void mma_fp16(float* c, const uint32_t* a,
                                         uint32_t b0, uint32_t b1) {
    asm volatile(
        "mma.sync.aligned.m16n8k16.row.col.f32.f16.f16.f32 "
        "{%0,%1,%2,%3}, {%4,%5,%6,%7}, {%8,%9}, {%0,%1,%2,%3};\n"
        : "+f"(c[0]), "+f"(c[1]), "+f"(c[2]), "+f"(c[3])
        : "r"(a[0]), "r"(a[1]), "r"(a[2]), "r"(a[3]), "r"(b0), "r"(b1));
}

#define CP_ASYNC16(dst, src) \
    asm volatile("cp.async.ca.shared.global [%0], [%1], 16;" :: "r"(dst), "l"(src))
#define CP_COMMIT() asm volatile("cp.async.commit_group;" ::: "memory")
#define CP_WAIT1()  asm volatile("cp.async.wait_group 1;" ::: "memory")

// split float4 into fp16 hi / fp16 lo (each packed as 2x half2 -> uint2)
__device__ __forceinline__ void split4h(float4 v, uint2& hi, uint2& lo) {
    __half hx = __float2half_rn(v.x);
    __half hy = __float2half_rn(v.y);
    __half hz = __float2half_rn(v.z);
    __half hw = __float2half_rn(v.w);
    __half lx = __float2half_rn(v.x - __half2float(hx));
    __half ly = __float2half_rn(v.y - __half2float(hy));
    __half lz = __float2half_rn(v.z - __half2float(hz));
    __half lw = __float2half_rn(v.w - __half2float(hw));
    __half2 h01 = __halves2half2(hx, hy);
    __half2 h23 = __halves2half2(hz, hw);
    __half2 l01 = __halves2half2(lx, ly);
    __half2 l23 = __halves2half2(lz, lw);
    hi.x = *reinterpret_cast<uint32_t*>(&h01);
    hi.y = *reinterpret_cast<uint32_t*>(&h23);
    lo.x = *reinterpret_cast<uint32_t*>(&l01);
    lo.y = *reinterpret_cast<uint32_t*>(&l23);
}

// ======================= K1: fused prep =====================================
// blocks [0,256):   x split -> g_ah/g_al, temporal_sum, spatial-sum partials
//                   (blocks 0..7 additionally zero BN accumulators)
// blocks [256,4352): W split -> g_wh/g_wl
__global__ __launch_bounds__(256)
void prep_kernel(const float* __restrict__ x, const float* __restrict__ W) {
    const int tid = threadIdx.x;
    if (blockIdx.x >= 256) {
        int idx4 = (blockIdx.x - 256) * 256 + tid;   // float4 index into [N,N]
        float4 v = reinterpret_cast<const float4*>(W)[idx4];
        uint2 hi, lo;
        split4h(v, hi, lo);
        reinterpret_cast<uint2*>(g_wh)[idx4] = hi;
        reinterpret_cast<uint2*>(g_wl)[idx4] = lo;
        return;
    }

    // ---- x-side block ----
    int gidx = blockIdx.x * 256 + tid;
    if (gidx < N_) { g_colsum[gidx] = 0.f; g_colsq[gidx] = 0.f; }

    __shared__ float red[T_][8];
    const int idx4 = blockIdx.x * 256 + tid;         // float4 index into [B,N]
    const int wid  = tid >> 5;
    const int lane = tid & 31;
    const float4* x4 = reinterpret_cast<const float4*>(x);
    uint2* ah2 = reinterpret_cast<uint2*>(g_ah);
    uint2* al2 = reinterpret_cast<uint2*>(g_al);

    float4 ts = make_float4(0.f, 0.f, 0.f, 0.f);
    #pragma unroll
    for (int t = 0; t < T_; t++) {
        size_t off = (size_t)t * (BN_ / 4) + idx4;
        float4 v = x4[off];
        ts.x += v.x; ts.y += v.y; ts.z += v.z; ts.w += v.w;
        uint2 hi, lo;
        split4h(v, hi, lo);
        ah2[off] = hi;
        al2[off] = lo;
        float s = v.x + v.y + v.z + v.w;
        #pragma unroll
        for (int o = 16; o > 0; o >>= 1)
            s += __shfl_down_sync(0xffffffffu, s, o);
        if (lane == 0) red[t][wid] = s;
    }
    reinterpret_cast<float4*>(g_tsum)[idx4] = ts;
    __syncthreads();
    if (tid < T_) {
        float s = 0.f;
        #pragma unroll
        for (int w = 0; w < 8; w++) s += red[tid][w];
        g_sspart[tid * 256 + blockIdx.x] = s;        // [t][b*2+half]
    }
}

// ======================= K2: mma.sync fp16x3 GEMM (pre-split) ===============
// h[r,m] = sum_k x[r,k] * W[m,k].
// CTA tile 128(M) x 128(N) x 32(K), 256 threads = 8 warps (2x4), warp 64x32.
// fp16 planes pre-split in gmem; hot loop is pure cp.async + LDSM + MMA.
// Epilogue fuses BN column statistics via shfl-reduce + atomics.
#define BK      32
#define HPITCH  40                      // halfs per smem row (32 + 8 pad)
#define PLANEB  (128 * HPITCH * 2)      // 10240 bytes per plane
#define STAGEB  (4 * PLANEB)            // A_hi, A_lo, B_hi, B_lo: 40960 B
#define GEMM_SMEM (2 * STAGEB)          // 81920 bytes

__global__ __launch_bounds__(256, 2)
void gemm_mma_kernel(float* __restrict__ C) {
    extern __shared__ char smc[];
    const uint32_t sbase = smem_u32(smc);
    const int tid  = threadIdx.x;
    const int wid  = tid >> 5;
    const int lane = tid & 31;
    const int wm = wid >> 2;            // 0..1 -> 64-row slab
    const int wn = wid & 3;             // 0..3 -> 32-col slab
    const int rowBase = blockIdx.y * 128;
    const int colBase = blockIdx.x * 128;

    float acc[4][4][4];
    #pragma unroll
    for (int i = 0; i < 4; i++)
        #pragma unroll
        for (int j = 0; j < 4; j++)
            #pragma unroll
            for (int c = 0; c < 4; c++) acc[i][j][c] = 0.f;

    // ---- cp.async loader: thread -> (row, 16-half part) ----
    const int lrow = tid >> 1;                  // 0..127
    const int part = (tid & 1) * 16;            // half offset within row
    const __half* pAh = g_ah + (size_t)(rowBase + lrow) * N_ + part;
    const __half* pAl = g_al + (size_t)(rowBase + lrow) * N_ + part;
    const __half* pBh = g_wh + (size_t)(colBase + lrow) * N_ + part;
    const __half* pBl = g_wl + (size_t)(colBase + lrow) * N_ + part;
    const uint32_t dRow = (uint32_t)((lrow * HPITCH + part) * 2);

    // ---- ldmatrix per-lane byte offsets ----
    const uint32_t aLane = (uint32_t)((((lane & 15) * HPITCH) + (lane >> 4) * 8) * 2);
    const uint32_t bLane = (uint32_t)(((((lane & 7) + ((lane >> 4) & 1) * 8) * HPITCH)
                                       + ((lane >> 3) & 1) * 8) * 2);
    const uint32_t aBase = sbase + (uint32_t)((wm * 64) * HPITCH * 2) + aLane;
    const uint32_t bBase = sbase + 2 * PLANEB + (uint32_t)((wn * 32) * HPITCH * 2) + bLane;

    // ---- prologue: load chunks 0,1 ----
    #pragma unroll
    for (int s = 0; s < 2; s++) {
        const uint32_t d = sbase + s * STAGEB + dRow;
        const int ko = s * BK;
        CP_ASYNC16(d,                       pAh + ko);
        CP_ASYNC16(d + 16,                  pAh + ko + 8);
        CP_ASYNC16(d + PLANEB,              pAl + ko);
        CP_ASYNC16(d + PLANEB + 16,         pAl + ko + 8);
        CP_ASYNC16(d + 2 * PLANEB,          pBh + ko);
        CP_ASYNC16(d + 2 * PLANEB + 16,     pBh + ko + 8);
        CP_ASYNC16(d + 3 * PLANEB,          pBl + ko);
        CP_ASYNC16(d + 3 * PLANEB + 16,     pBl + ko + 8);
        CP_COMMIT();
    }

    const int NCHUNK = N_ / BK;          // 64
    #pragma unroll 1
    for (int kc = 0; kc < NCHUNK; kc++) {
        const int st = kc & 1;
        CP_WAIT1();
        __syncthreads();

        const uint32_t aS = aBase + st * STAGEB;
        const uint32_t bS = bBase + st * STAGEB;

        #pragma unroll
        for (int ks = 0; ks < 2; ks++) {
            const uint32_t kb = ks * 32;   // 16 halfs = 32 bytes
            uint32_t bh[2][4], bl[2][4];
            #pragma unroll
            for (int jp = 0; jp < 2; jp++) {
                ldsm_x4(bS + kb + jp * (16 * HPITCH * 2),
                        bh[jp][0], bh[jp][1], bh[jp][2], bh[jp][3]);
                ldsm_x4(bS + PLANEB + kb + jp * (16 * HPITCH * 2),
                        bl[jp][0], bl[jp][1], bl[jp][2], bl[jp][3]);
            }
            #pragma unroll
            for (int i = 0; i < 4; i++) {
                uint32_t ah[4], al[4];
                ldsm_x4(aS + kb + i * (16 * HPITCH * 2), ah[0], ah[1], ah[2], ah[3]);
                ldsm_x4(aS + PLANEB + kb + i * (16 * HPITCH * 2), al[0], al[1], al[2], al[3]);
                #pragma unroll
                for (int j = 0; j < 4; j++)
                    mma_fp16(acc[i][j], ah, bh[j >> 1][(j & 1) * 2], bh[j >> 1][(j & 1) * 2 + 1]);
                #pragma unroll
                for (int j = 0; j < 4; j++)
                    mma_fp16(acc[i][j], al, bh[j >> 1][(j & 1) * 2], bh[j >> 1][(j & 1) * 2 + 1]);
                #pragma unroll
                for (int j = 0; j < 4; j++)
                    mma_fp16(acc[i][j], ah, bl[j >> 1][(j & 1) * 2], bl[j >> 1][(j & 1) * 2 + 1]);
            }
        }
        __syncthreads();

        // refill the consumed stage with chunk kc+2
        if (kc + 2 < NCHUNK) {
            const uint32_t d = sbase + st * STAGEB + dRow;
            const int ko = (kc + 2) * BK;
            CP_ASYNC16(d,                       pAh + ko);
            CP_ASYNC16(d + 16,                  pAh + ko + 8);
            CP_ASYNC16(d + PLANEB,              pAl + ko);
            CP_ASYNC16(d + PLANEB + 16,         pAl + ko + 8);
            CP_ASYNC16(d + 2 * PLANEB,          pBh + ko);
            CP_ASYNC16(d + 2 * PLANEB + 16,     pBh + ko + 8);
            CP_ASYNC16(d + 3 * PLANEB,          pBl + ko);
            CP_ASYNC16(d + 3 * PLANEB + 16,     pBl + ko + 8);
        }
        CP_COMMIT();
    }

    // ---- epilogue: write 128x128 tile + fused BN column stats ----
    const int gid = lane >> 2;
    const int qd  = lane & 3;
    const int m0 = rowBase + wm * 64 + gid;
    const int n0 = colBase + wn * 32 + 2 * qd;
    #pragma unroll
    for (int i = 0; i < 4; i++) {
        #pragma unroll
        for (int jj = 0; jj < 4; jj++) {
            float* p = C + (size_t)(m0 + 16 * i) * N_ + n0 + 8 * jj;
            float2 v01 = make_float2(acc[i][jj][0], acc[i][jj][1]);
            float2 v23 = make_float2(acc[i][jj][2], acc[i][jj][3]);
            *reinterpret_cast<float2*>(p)          = v01;
            *reinterpret_cast<float2*>(p + 8 * N_) = v23;
        }
    }

    // column sums / sums-of-squares over this warp's 64 rows
    float s[4][2], q[4][2];
    #pragma unroll
    for (int j = 0; j < 4; j++) {
        s[j][0] = s[j][1] = q[j][0] = q[j][1] = 0.f;
        #pragma unroll
        for (int i = 0; i < 4; i++) {
            s[j][0] += acc[i][j][0] + acc[i][j][2];
            s[j][1] += acc[i][j][1] + acc[i][j][3];
            q[j][0] += acc[i][j][0] * acc[i][j][0] + acc[i][j][2] * acc[i][j][2];
            q[j][1] += acc[i][j][1] * acc[i][j][1] + acc[i][j][3] * acc[i][j][3];
        }
    }
    #pragma unroll
    for (int j = 0; j < 4; j++)
        #pragma unroll
        for (int c = 0; c < 2; c++) {
            #pragma unroll
            for (int off = 16; off >= 4; off >>= 1) {
                s[j][c] += __shfl_down_sync(0xffffffffu, s[j][c], off);
                q[j][c] += __shfl_down_sync(0xffffffffu, q[j][c], off);
            }
        }
    if (lane < 4) {
        #pragma unroll
        for (int j = 0; j < 4; j++)
            #pragma unroll
            for (int c = 0; c < 2; c++) {
                int col = colBase + wn * 32 + 2 * lane + 8 * j + c;
                atomicAdd(&g_colsum[col], s[j][c]);
                atomicAdd(&g_colsq[col],  q[j][c]);
            }
    }
}

// ======================= K3: fused BN + 3x LIF + combine ====================
__global__ __launch_bounds__(256)
void fused_lif_kernel(const float* __restrict__ x,
                      const float* __restrict__ gamma,
                      const float* __restrict__ beta,
                      float* __restrict__ out) {
    int idx4 = blockIdx.x * 256 + threadIdx.x;   // float4 index into [B,N]
    int b  = idx4 >> 9;
    int n4 = idx4 & 511;

    float4 cs4 = reinterpret_cast<const float4*>(g_colsum)[n4];
    float4 cq4 = reinterpret_cast<const float4*>(g_colsq)[n4];
    float4 ga4 = reinterpret_cast<const float4*>(gamma)[n4];
    float4 be4 = reinterpret_cast<const float4*>(beta)[n4];
    float4 ts4 = reinterpret_cast<const float4*>(g_tsum)[idx4];

    const float inv = 1.0f / TB_;
    float mu[4]    = {cs4.x * inv, cs4.y * inv, cs4.z * inv, cs4.w * inv};
    float var[4]   = {cq4.x * inv - mu[0] * mu[0], cq4.y * inv - mu[1] * mu[1],
                      cq4.z * inv - mu[2] * mu[2], cq4.w * inv - mu[3] * mu[3]};
    float scale[4] = {ga4.x * rsqrtf(var[0] + 1e-5f), ga4.y * rsqrtf(var[1] + 1e-5f),
                      ga4.z * rsqrtf(var[2] + 1e-5f), ga4.w * rsqrtf(var[3] + 1e-5f)};
    float bet[4]   = {be4.x, be4.y, be4.z, be4.w};
    float ts[4]    = {ts4.x, ts4.y, ts4.z, ts4.w};

    float v1[4] = {0, 0, 0, 0}, v2[4] = {0, 0, 0, 0}, v3[4] = {0, 0, 0, 0};
    const float4* h4 = reinterpret_cast<const float4*>(g_h);
    const float4* x4 = reinterpret_cast<const float4*>(x);
    float4* o4 = reinterpret_cast<float4*>(out);

    #pragma unroll
    for (int t = 0; t < T_; t++) {
        size_t off = (size_t)t * (BN_ / 4) + idx4;
        float4 hv = h4[off];
        float4 xv = x4[off];
        float hh[4] = {hv.x, hv.y, hv.z, hv.w};
        float xx[4] = {xv.x, xv.y, xv.z, xv.w};
        float ss = g_sspart[t * 256 + b * 2] + g_sspart[t * 256 + b * 2 + 1];
        float res[4];
        #pragma unroll
        for (int j = 0; j < 4; j++) {
            float hn = (hh[j] - mu[j]) * scale[j] + bet[j];
            v1[j] = 0.5f * v1[j] + hn;
            float s1 = (v1[j] >= 1.0f) ? 1.0f : 0.0f;
            v1[j] = (v1[j] >= 1.0f) ? 0.0f : v1[j];
            v2[j] = 0.5f * v2[j] + s1 * ss;
            float s2 = (v2[j] >= 1.0f) ? 1.0f : 0.0f;
            v2[j] = (v2[j] >= 1.0f) ? 0.0f : v2[j];
            v3[j] = 0.5f * v3[j] + s1 * ts[j];
            float s3 = (v3[j] >= 1.0f) ? 1.0f : 0.0f;
            v3[j] = (v3[j] >= 1.0f) ? 0.0f : v3[j];
            res[j] = xx[j] + s2 * s3;
        }
        o4[off] = make_float4(res[0], res[1], res[2], res[3]);
    }
}

// ======================= launch =============================================
extern "C" void kernel_launch(void* const* d_in, const int* in_sizes, int n_in,
                              void* d_out, int out_size) {
    const float* x     = (const float*)d_in[0];   // [T,B,N]
    const float* W     = (const float*)d_in[1];   // [N,N]
    const float* gamma = (const float*)d_in[2];
    const float* beta  = (const float*)d_in[3];
    float* out = (float*)d_out;

    float* h;
    cudaGetSymbolAddress((void**)&h, g_h);

    cudaFuncSetAttribute(gemm_mma_kernel,
                         cudaFuncAttributeMaxDynamicSharedMemorySize, GEMM_SMEM);

    prep_kernel<<<256 + (N_ * N_) / 1024, 256>>>(x, W);

    dim3 gemmGrid(N_ / 128, TB_ / 128);
    gemm_mma_kernel<<<gemmGrid, 256, GEMM_SMEM>>>(h);

    fused_lif_kernel<<<BN_ / 1024, 256>>>(x, gamma, beta, out);
}